// round 8
// baseline (speedup 1.0000x reference)
#include <cuda_runtime.h>

#define N_NODES 10000
#define N_EDGES 160000

// ---------------- scratch (static device globals; no allocation) ----------
static __device__ float g_up_s[N_NODES * 128];   // up_s [n][j]
static __device__ float g_up_v[N_NODES * 384];   // up_v [n][c*128 + j]
static __device__ float g_down[N_NODES * 64];    // down [n][j]
static __device__ float g_m0[N_NODES * 256];     // segment sums mid0
static __device__ float g_m1[N_NODES * 768];     // segment sums mid1 [n][c*256 + i]

#define INV_SQRT_C   0.08838834764831845f   // 1/sqrt(128)
#define INV_SQRT_AUG 0.08574929257125442f   // 1/sqrt(136)
#define SIXTEENTH    0.0625f                // 1/sqrt(256)
#define INV_SQRT3    0.5773502691896258f
#define FINAL_SCALE  0.00390625f            // 1/(sqrt(256)*16)

typedef unsigned long long ull;

__device__ __forceinline__ float act_silu(float a, float scale) {
    float y = a * scale;
    return y / (1.0f + __expf(-y));
}

// ---- packed f32x2 helpers (FFMA2: 2x fp32 throughput, exact fp32) --------
__device__ __forceinline__ ull bcast2(float x) {
    ull r; asm("mov.b64 %0, {%1, %1};" : "=l"(r) : "f"(x)); return r;
}
__device__ __forceinline__ ull ffma2(ull a, ull b, ull c) {
    ull d; asm("fma.rn.f32x2 %0, %1, %2, %3;" : "=l"(d) : "l"(a), "l"(b), "l"(c));
    return d;
}
__device__ __forceinline__ float2 unpack2(ull v) {
    float2 f; asm("mov.b64 {%0, %1}, %2;" : "=f"(f.x), "=f"(f.y) : "l"(v));
    return f;
}

// ---------------- zero scratch ---------------------------------------------
__global__ void zero_kernel() {
    float4 z = make_float4(0.f, 0.f, 0.f, 0.f);
    float4* p0 = (float4*)g_m0;
    float4* p1 = (float4*)g_m1;
    const int n0 = N_NODES * 256 / 4;
    const int n1 = N_NODES * 768 / 4;
    int idx = blockIdx.x * blockDim.x + threadIdx.x;
    int stride = gridDim.x * blockDim.x;
    for (int k = idx; k < n0; k += stride) p0[k] = z;
    for (int k = idx; k < n1; k += stride) p1[k] = z;
}

// ---------------- node pre-pass --------------------------------------------
__device__ __forceinline__ void dual_gemv_128(const float* __restrict__ Xs,
                                              const float* __restrict__ WA,
                                              const float* __restrict__ WB,
                                              int j, int g,
                                              float* accA, float* accB)
{
#pragma unroll
    for (int m = 0; m < 16; m++) { accA[m] = 0.f; accB[m] = 0.f; }
    for (int k = 0; k < 128; k += 4) {
        float a0 = WA[(k + 0) * 128 + j];
        float a1 = WA[(k + 1) * 128 + j];
        float a2 = WA[(k + 2) * 128 + j];
        float a3 = WA[(k + 3) * 128 + j];
        float b0 = WB[(k + 0) * 128 + j];
        float b1 = WB[(k + 1) * 128 + j];
        float b2 = WB[(k + 2) * 128 + j];
        float b3 = WB[(k + 3) * 128 + j];
#pragma unroll
        for (int m = 0; m < 16; m++) {
            float4 x = *(const float4*)(Xs + (g + 2 * m) * 128 + k);
            accA[m] = fmaf(x.x, a0, accA[m]);
            accA[m] = fmaf(x.y, a1, accA[m]);
            accA[m] = fmaf(x.z, a2, accA[m]);
            accA[m] = fmaf(x.w, a3, accA[m]);
            accB[m] = fmaf(x.x, b0, accB[m]);
            accB[m] = fmaf(x.y, b1, accB[m]);
            accB[m] = fmaf(x.z, b2, accB[m]);
            accB[m] = fmaf(x.w, b3, accB[m]);
        }
    }
}

__global__ __launch_bounds__(256, 1) void node_pre_kernel(
    const float* __restrict__ node_feats,
    const float* __restrict__ W_up0, const float* __restrict__ W_up1,
    const float* __restrict__ W_down,
    const float* __restrict__ W_skip0, const float* __restrict__ W_skip1,
    float* __restrict__ out_sc)
{
    extern __shared__ float sm[];
    float* s = sm;              // 32*128
    float* v = sm + 32 * 128;   // 3 planes of 32*128: [c][n][i]
    const int nbase = blockIdx.x * 32;
    const int t = threadIdx.x;

    for (int idx = t; idx < 32 * 512; idx += 256) {
        int nl = idx >> 9;
        int f  = idx & 511;
        int n  = nbase + nl;
        float val = (n < N_NODES) ? node_feats[(size_t)n * 512 + f] : 0.f;
        if (f < 128) {
            s[nl * 128 + f] = val;
        } else {
            int r = f - 128;
            int i = r / 3;
            int c = r - 3 * i;
            v[c * (32 * 128) + nl * 128 + i] = val;
        }
    }
    __syncthreads();

    const int j = t & 127;
    const int g = t >> 7;

    {
        float accA[16], accB[16];
        dual_gemv_128(s, W_skip0, W_up0, j, g, accA, accB);
#pragma unroll
        for (int m = 0; m < 16; m++) {
            int n = nbase + g + 2 * m;
            if (n < N_NODES) {
                out_sc[(size_t)n * 512 + j] = accA[m] * INV_SQRT_C;
                g_up_s[n * 128 + j]         = accB[m] * INV_SQRT_C;
            }
        }
    }
    {
        int jd = t & 63;
        int gd = t >> 6;
        float acc[8];
#pragma unroll
        for (int m = 0; m < 8; m++) acc[m] = 0.f;
        for (int k = 0; k < 128; k += 4) {
            float w0 = W_down[(k + 0) * 64 + jd];
            float w1 = W_down[(k + 1) * 64 + jd];
            float w2 = W_down[(k + 2) * 64 + jd];
            float w3 = W_down[(k + 3) * 64 + jd];
#pragma unroll
            for (int m = 0; m < 8; m++) {
                float4 x = *(const float4*)(s + (gd + 4 * m) * 128 + k);
                acc[m] = fmaf(x.x, w0, acc[m]);
                acc[m] = fmaf(x.y, w1, acc[m]);
                acc[m] = fmaf(x.z, w2, acc[m]);
                acc[m] = fmaf(x.w, w3, acc[m]);
            }
        }
#pragma unroll
        for (int m = 0; m < 8; m++) {
            int n = nbase + gd + 4 * m;
            if (n < N_NODES) g_down[n * 64 + jd] = acc[m] * INV_SQRT_C;
        }
    }
    for (int c = 0; c < 3; c++) {
        const float* vp = v + c * (32 * 128);
        float accA[16], accB[16];
        dual_gemv_128(vp, W_skip1, W_up1, j, g, accA, accB);
#pragma unroll
        for (int m = 0; m < 16; m++) {
            int n = nbase + g + 2 * m;
            if (n < N_NODES) {
                out_sc[(size_t)n * 512 + 128 + j * 3 + c] = accA[m] * INV_SQRT_C;
                g_up_v[n * 384 + c * 128 + j]             = accB[m] * INV_SQRT_C;
            }
        }
    }
}

// ---------------- edge MLP (packed f32x2) -----------------------------------
// Activation smem layout (per 16-edge group g, pairing edges (i, i+8)):
//   X[g*16*K + i*2*K + 2*k + p]  ,  i in [0,8), p in {0,1}
// One ulonglong2 (LDS.128) at (g,i,2k) = packed f32x2 pairs for rows k, k+1.
template <int K>
__device__ __forceinline__ void mlp_layer2(const float* __restrict__ X,
                                           const float* __restrict__ W,
                                           float* __restrict__ Y,
                                           float scale)
{
    const int t  = threadIdx.x;
    const int j0 = (t & 63) * 4;
    const int g  = t >> 6;
    ull acc[8][4];
#pragma unroll
    for (int i = 0; i < 8; i++) {
#pragma unroll
        for (int c = 0; c < 4; c++) acc[i][c] = 0ULL;
    }
    const float* xb = X + g * 16 * K;
#pragma unroll 2
    for (int k = 0; k < K; k += 2) {
        float4 wa = *(const float4*)(W + (size_t)(k + 0) * 256 + j0);
        float4 wb = *(const float4*)(W + (size_t)(k + 1) * 256 + j0);
        ull wa0 = bcast2(wa.x), wa1 = bcast2(wa.y), wa2 = bcast2(wa.z), wa3 = bcast2(wa.w);
        ull wb0 = bcast2(wb.x), wb1 = bcast2(wb.y), wb2 = bcast2(wb.z), wb3 = bcast2(wb.w);
#pragma unroll
        for (int i = 0; i < 8; i++) {
            ulonglong2 xv = *(const ulonglong2*)(xb + i * 2 * K + 2 * k);
            acc[i][0] = ffma2(xv.x, wa0, acc[i][0]);
            acc[i][1] = ffma2(xv.x, wa1, acc[i][1]);
            acc[i][2] = ffma2(xv.x, wa2, acc[i][2]);
            acc[i][3] = ffma2(xv.x, wa3, acc[i][3]);
            acc[i][0] = ffma2(xv.y, wb0, acc[i][0]);
            acc[i][1] = ffma2(xv.y, wb1, acc[i][1]);
            acc[i][2] = ffma2(xv.y, wb2, acc[i][2]);
            acc[i][3] = ffma2(xv.y, wb3, acc[i][3]);
        }
    }
    // silu + write back in packed layout (K_out = 256); the thread's 8 floats
    // per pair are contiguous: [2*j0 .. 2*j0+7] -> two STS.128.
    float* yb = Y + g * 16 * 256;
#pragma unroll
    for (int i = 0; i < 8; i++) {
        float2 v0 = unpack2(acc[i][0]);
        float2 v1 = unpack2(acc[i][1]);
        float2 v2 = unpack2(acc[i][2]);
        float2 v3 = unpack2(acc[i][3]);
        float4 o0, o1;
        o0.x = act_silu(v0.x, scale); o0.y = act_silu(v0.y, scale);
        o0.z = act_silu(v1.x, scale); o0.w = act_silu(v1.y, scale);
        o1.x = act_silu(v2.x, scale); o1.y = act_silu(v2.y, scale);
        o1.z = act_silu(v3.x, scale); o1.w = act_silu(v3.y, scale);
        *(float4*)(yb + i * 512 + 2 * j0)     = o0;
        *(float4*)(yb + i * 512 + 2 * j0 + 4) = o1;
    }
}

// Layer 3 (N=512) fused with tensor product + atomic scatter, f32x2 version.
// Per pass: 32 edges (2 groups of 16), thread map j = t&127, eg = t>>7.
__device__ __forceinline__ void final_layer_tp2(const float* __restrict__ H,
                                                const float* __restrict__ Wm3,
                                                const int* __restrict__ sidx,
                                                const int* __restrict__ ridx,
                                                const float* __restrict__ eattr)
{
    const int t  = threadIdx.x;
    const int j  = t & 127;
    const int eg = t >> 7;
#pragma unroll 1
    for (int p = 0; p < 2; p++) {
        const int e0 = p * 32 + eg * 16;
        const int gq = e0 >> 4;
        ull a1[8], a2[8], a3[8], a4[8];
#pragma unroll
        for (int i = 0; i < 8; i++) { a1[i] = 0ULL; a2[i] = 0ULL; a3[i] = 0ULL; a4[i] = 0ULL; }
        const float* xb = H + gq * 16 * 256;
#pragma unroll 2
        for (int k = 0; k < 256; k += 2) {
            const float* wr0 = Wm3 + (size_t)k * 512;
            const float* wr1 = wr0 + 512;
            ull w1a = bcast2(wr0[j]),       w1b = bcast2(wr1[j]);
            ull w2a = bcast2(wr0[128 + j]), w2b = bcast2(wr1[128 + j]);
            ull w3a = bcast2(wr0[256 + j]), w3b = bcast2(wr1[256 + j]);
            ull w4a = bcast2(wr0[384 + j]), w4b = bcast2(wr1[384 + j]);
#pragma unroll
            for (int i = 0; i < 8; i++) {
                ulonglong2 xv = *(const ulonglong2*)(xb + i * 512 + 2 * k);
                a1[i] = ffma2(xv.x, w1a, a1[i]);
                a2[i] = ffma2(xv.x, w2a, a2[i]);
                a3[i] = ffma2(xv.x, w3a, a3[i]);
                a4[i] = ffma2(xv.x, w4a, a4[i]);
                a1[i] = ffma2(xv.y, w1b, a1[i]);
                a2[i] = ffma2(xv.y, w2b, a2[i]);
                a3[i] = ffma2(xv.y, w3b, a3[i]);
                a4[i] = ffma2(xv.y, w4b, a4[i]);
            }
        }
#pragma unroll 1
        for (int i = 0; i < 8; i++) {
            float2 w1v = unpack2(a1[i]);
            float2 w2v = unpack2(a2[i]);
            float2 w3v = unpack2(a3[i]);
            float2 w4v = unpack2(a4[i]);
#pragma unroll 1
            for (int pp = 0; pp < 2; pp++) {
                int e   = e0 + i + pp * 8;
                int snd = sidx[e];
                int rcv = ridx[e];
                float xs  = g_up_s[snd * 128 + j];
                float xv0 = g_up_v[snd * 384 + j];
                float xv1 = g_up_v[snd * 384 + 128 + j];
                float xv2 = g_up_v[snd * 384 + 256 + j];
                float y0  = eattr[e * 4 + 0];
                float yv0 = eattr[e * 4 + 1];
                float yv1 = eattr[e * 4 + 2];
                float yv2 = eattr[e * 4 + 3];
                float w1 = (pp ? w1v.y : w1v.x) * SIXTEENTH;
                float w2 = (pp ? w2v.y : w2v.x) * SIXTEENTH;
                float w3 = (pp ? w3v.y : w3v.x) * SIXTEENTH;
                float w4 = (pp ? w4v.y : w4v.x) * SIXTEENTH;

                float out0a = w1 * xs * y0;
                float dotxy = xv0 * yv0 + xv1 * yv1 + xv2 * yv2;
                float out0b = w4 * dotxy * INV_SQRT3;
                float* m0r = g_m0 + (size_t)rcv * 256;
                atomicAdd(m0r + j, out0a);
                atomicAdd(m0r + 128 + j, out0b);

                float w2xs = w2 * xs;
                float w3y0 = w3 * y0;
                float* m1r = g_m1 + (size_t)rcv * 768;
                atomicAdd(m1r +   0 + j, w2xs * yv0);
                atomicAdd(m1r + 256 + j, w2xs * yv1);
                atomicAdd(m1r + 512 + j, w2xs * yv2);
                atomicAdd(m1r + 128 + j, w3y0 * xv0);
                atomicAdd(m1r + 384 + j, w3y0 * xv1);
                atomicAdd(m1r + 640 + j, w3y0 * xv2);
            }
        }
    }
}

#define EDGE_SMEM_BYTES ((64 * 136 + 2 * 64 * 256) * 4 + 128 * 4 + 64 * 4 * 4)

__global__ __launch_bounds__(256, 1) void edge_kernel(
    const float* __restrict__ edge_attrs,
    const float* __restrict__ edge_feats,
    const int* __restrict__ edge_index,
    const float* __restrict__ Wm0, const float* __restrict__ Wm1,
    const float* __restrict__ Wm2, const float* __restrict__ Wm3)
{
    extern __shared__ float sm[];
    float* aug = sm;                       // 64*136  (packed pair layout)
    float* h0  = aug + 64 * 136;           // 64*256  (packed)
    float* h1  = h0 + 64 * 256;            // 64*256  (packed)
    int*   sidx = (int*)(h1 + 64 * 256);   // 64
    int*   ridx = sidx + 64;               // 64
    float* eattr = (float*)(ridx + 64);    // 64*4

    const int t = threadIdx.x;
    const int ebase = blockIdx.x * 64;

    if (t < 64) {
        sidx[t] = edge_index[(size_t)(ebase + t) * 2];
        ridx[t] = edge_index[(size_t)(ebase + t) * 2 + 1];
    }
    for (int idx = t; idx < 64 * 4; idx += 256)
        eattr[idx] = edge_attrs[(size_t)ebase * 4 + idx];
    __syncthreads();

    // build aug = [edge_feats(8) | down[sender](64) | down[receiver](64)]
    // written directly in packed pair layout: addr(e,f) with e = g*16 + i + 8p
    for (int idx = t; idx < 64 * 136; idx += 256) {
        int e = idx / 136;
        int f = idx - e * 136;
        float val;
        if (f < 8)       val = edge_feats[(size_t)(ebase + e) * 8 + f];
        else if (f < 72) val = g_down[sidx[e] * 64 + (f - 8)];
        else             val = g_down[ridx[e] * 64 + (f - 72)];
        int g2 = e >> 4;
        int r  = e & 15;
        int i  = r & 7;
        int pp = r >> 3;
        aug[g2 * (16 * 136) + i * 272 + 2 * f + pp] = val;
    }
    __syncthreads();

    mlp_layer2<136>(aug, Wm0, h0, INV_SQRT_AUG);
    __syncthreads();
    mlp_layer2<256>(h0, Wm1, h1, SIXTEENTH);
    __syncthreads();
    mlp_layer2<256>(h1, Wm2, h0, SIXTEENTH);
    __syncthreads();
    final_layer_tp2(h0, Wm3, sidx, ridx, eattr);
}

// ---------------- node post-pass --------------------------------------------
__global__ __launch_bounds__(256, 2) void node_post_kernel(
    const float* __restrict__ W_lin0,
    const float* __restrict__ W_lin1,
    float* __restrict__ out)
{
    __shared__ float tile[32 * 256];
    const int nbase = blockIdx.x * 32;
    const int t = threadIdx.x;
    const int j = t & 127;
    const int g = t >> 7;

    for (int idx = t; idx < 32 * 256; idx += 256) {
        int nl = idx >> 8;
        int k  = idx & 255;
        int n  = nbase + nl;
        tile[idx] = (n < N_NODES) ? g_m0[(size_t)n * 256 + k] : 0.f;
    }
    __syncthreads();
    {
        float acc[16];
#pragma unroll
        for (int m = 0; m < 16; m++) acc[m] = 0.f;
        for (int k = 0; k < 256; k += 4) {
            float w0 = W_lin0[(k + 0) * 128 + j];
            float w1 = W_lin0[(k + 1) * 128 + j];
            float w2 = W_lin0[(k + 2) * 128 + j];
            float w3 = W_lin0[(k + 3) * 128 + j];
#pragma unroll
            for (int m = 0; m < 16; m++) {
                float4 x = *(const float4*)(tile + (g + 2 * m) * 256 + k);
                acc[m] = fmaf(x.x, w0, acc[m]);
                acc[m] = fmaf(x.y, w1, acc[m]);
                acc[m] = fmaf(x.z, w2, acc[m]);
                acc[m] = fmaf(x.w, w3, acc[m]);
            }
        }
#pragma unroll
        for (int m = 0; m < 16; m++) {
            int n = nbase + g + 2 * m;
            if (n < N_NODES) out[(size_t)n * 512 + j * 4 + 0] = acc[m] * FINAL_SCALE;
        }
    }
    for (int c = 0; c < 3; c++) {
        __syncthreads();
        for (int idx = t; idx < 32 * 256; idx += 256) {
            int nl = idx >> 8;
            int k  = idx & 255;
            int n  = nbase + nl;
            tile[idx] = (n < N_NODES) ? g_m1[(size_t)n * 768 + c * 256 + k] : 0.f;
        }
        __syncthreads();
        float acc[16];
#pragma unroll
        for (int m = 0; m < 16; m++) acc[m] = 0.f;
        for (int k = 0; k < 256; k += 4) {
            float w0 = W_lin1[(k + 0) * 128 + j];
            float w1 = W_lin1[(k + 1) * 128 + j];
            float w2 = W_lin1[(k + 2) * 128 + j];
            float w3 = W_lin1[(k + 3) * 128 + j];
#pragma unroll
            for (int m = 0; m < 16; m++) {
                float4 x = *(const float4*)(tile + (g + 2 * m) * 256 + k);
                acc[m] = fmaf(x.x, w0, acc[m]);
                acc[m] = fmaf(x.y, w1, acc[m]);
                acc[m] = fmaf(x.z, w2, acc[m]);
                acc[m] = fmaf(x.w, w3, acc[m]);
            }
        }
#pragma unroll
        for (int m = 0; m < 16; m++) {
            int n = nbase + g + 2 * m;
            if (n < N_NODES) out[(size_t)n * 512 + j * 4 + 1 + c] = acc[m] * FINAL_SCALE;
        }
    }
}

// ---------------- launch -----------------------------------------------------
extern "C" void kernel_launch(void* const* d_in, const int* in_sizes, int n_in,
                              void* d_out, int out_size)
{
    (void)in_sizes; (void)n_in; (void)out_size;
    const float* node_feats = (const float*)d_in[1];
    const float* edge_attrs = (const float*)d_in[2];
    const float* edge_feats = (const float*)d_in[3];
    const int*   edge_index = (const int*)d_in[4];
    const float* W_up0   = (const float*)d_in[5];
    const float* W_up1   = (const float*)d_in[6];
    const float* W_down  = (const float*)d_in[7];
    const float* Wm0     = (const float*)d_in[8];
    const float* Wm1     = (const float*)d_in[9];
    const float* Wm2     = (const float*)d_in[10];
    const float* Wm3     = (const float*)d_in[11];
    const float* W_lin0  = (const float*)d_in[12];
    const float* W_lin1  = (const float*)d_in[13];
    const float* W_skip0 = (const float*)d_in[14];
    const float* W_skip1 = (const float*)d_in[15];

    float* out    = (float*)d_out;                          // (N,128,4)
    float* out_sc = out + (size_t)N_NODES * 512;            // (N,512)

    cudaFuncSetAttribute(node_pre_kernel,
                         cudaFuncAttributeMaxDynamicSharedMemorySize, 64 * 1024);
    cudaFuncSetAttribute(edge_kernel,
                         cudaFuncAttributeMaxDynamicSharedMemorySize, EDGE_SMEM_BYTES);

    zero_kernel<<<512, 256>>>();
    node_pre_kernel<<<(N_NODES + 31) / 32, 256, 64 * 1024>>>(
        node_feats, W_up0, W_up1, W_down, W_skip0, W_skip1, out_sc);
    edge_kernel<<<N_EDGES / 64, 256, EDGE_SMEM_BYTES>>>(
        edge_attrs, edge_feats, edge_index, Wm0, Wm1, Wm2, Wm3);
    node_post_kernel<<<(N_NODES + 31) / 32, 256>>>(W_lin0, W_lin1, out);
}

// round 12
// speedup vs baseline: 1.0138x; 1.0138x over previous
#include <cuda_runtime.h>
#include <cuda_fp16.h>
#include <cstdint>

#define N_NODES 10000
#define N_EDGES 160000

static __device__ float g_up_s[N_NODES * 128];
static __device__ float g_up_v[N_NODES * 384];
static __device__ float g_down[N_NODES * 64];
static __device__ float g_m0[N_NODES * 256];
static __device__ float g_m1[N_NODES * 768];

#define INV_SQRT_C   0.08838834764831845f
#define INV_SQRT_AUG 0.08574929257125442f
#define SIXTEENTH    0.0625f
#define INV_SQRT3    0.5773502691896258f
#define FINAL_SCALE  0.00390625f

__device__ __forceinline__ float act_silu(float a, float scale) {
    float y = a * scale;
    return y / (1.0f + __expf(-y));
}

// ---------------- HMMA m16n8k16 fp16 -> fp32 --------------------------------
__device__ __forceinline__ void mma16816(float* c, const uint32_t* a, const uint32_t* b) {
    asm volatile(
        "mma.sync.aligned.m16n8k16.row.col.f32.f16.f16.f32 "
        "{%0,%1,%2,%3},{%4,%5,%6,%7},{%8,%9},{%0,%1,%2,%3};"
        : "+f"(c[0]), "+f"(c[1]), "+f"(c[2]), "+f"(c[3])
        : "r"(a[0]), "r"(a[1]), "r"(a[2]), "r"(a[3]), "r"(b[0]), "r"(b[1]));
}

// pack two halves into one b32 (low = a, high = b) — full 32-bit reinterpret.
__device__ __forceinline__ uint32_t pack_half2(__half a, __half b) {
    __half2 h = __halves2half2(a, b);
    return *reinterpret_cast<uint32_t*>(&h);
}

// ---------------- zero scratch ----------------------------------------------
__global__ void zero_kernel() {
    float4 z = make_float4(0.f, 0.f, 0.f, 0.f);
    float4* p0 = (float4*)g_m0;
    float4* p1 = (float4*)g_m1;
    const int n0 = N_NODES * 256 / 4;
    const int n1 = N_NODES * 768 / 4;
    int idx = blockIdx.x * blockDim.x + threadIdx.x;
    int stride = gridDim.x * blockDim.x;
    for (int k = idx; k < n0; k += stride) p0[k] = z;
    for (int k = idx; k < n1; k += stride) p1[k] = z;
}

// ---------------- node pre-pass (unchanged FFMA path) -----------------------
__device__ __forceinline__ void dual_gemv_128(const float* __restrict__ Xs,
                                              const float* __restrict__ WA,
                                              const float* __restrict__ WB,
                                              int j, int g,
                                              float* accA, float* accB)
{
#pragma unroll
    for (int m = 0; m < 16; m++) { accA[m] = 0.f; accB[m] = 0.f; }
    for (int k = 0; k < 128; k += 4) {
        float a0 = WA[(k + 0) * 128 + j];
        float a1 = WA[(k + 1) * 128 + j];
        float a2 = WA[(k + 2) * 128 + j];
        float a3 = WA[(k + 3) * 128 + j];
        float b0 = WB[(k + 0) * 128 + j];
        float b1 = WB[(k + 1) * 128 + j];
        float b2 = WB[(k + 2) * 128 + j];
        float b3 = WB[(k + 3) * 128 + j];
#pragma unroll
        for (int m = 0; m < 16; m++) {
            float4 x = *(const float4*)(Xs + (g + 2 * m) * 128 + k);
            accA[m] = fmaf(x.x, a0, accA[m]);
            accA[m] = fmaf(x.y, a1, accA[m]);
            accA[m] = fmaf(x.z, a2, accA[m]);
            accA[m] = fmaf(x.w, a3, accA[m]);
            accB[m] = fmaf(x.x, b0, accB[m]);
            accB[m] = fmaf(x.y, b1, accB[m]);
            accB[m] = fmaf(x.z, b2, accB[m]);
            accB[m] = fmaf(x.w, b3, accB[m]);
        }
    }
}

__global__ __launch_bounds__(256, 1) void node_pre_kernel(
    const float* __restrict__ node_feats,
    const float* __restrict__ W_up0, const float* __restrict__ W_up1,
    const float* __restrict__ W_down,
    const float* __restrict__ W_skip0, const float* __restrict__ W_skip1,
    float* __restrict__ out_sc)
{
    extern __shared__ float sm[];
    float* s = sm;
    float* v = sm + 32 * 128;
    const int nbase = blockIdx.x * 32;
    const int t = threadIdx.x;

    for (int idx = t; idx < 32 * 512; idx += 256) {
        int nl = idx >> 9;
        int f  = idx & 511;
        int n  = nbase + nl;
        float val = (n < N_NODES) ? node_feats[(size_t)n * 512 + f] : 0.f;
        if (f < 128) {
            s[nl * 128 + f] = val;
        } else {
            int r = f - 128;
            int i = r / 3;
            int c = r - 3 * i;
            v[c * (32 * 128) + nl * 128 + i] = val;
        }
    }
    __syncthreads();

    const int j = t & 127;
    const int g = t >> 7;
    {
        float accA[16], accB[16];
        dual_gemv_128(s, W_skip0, W_up0, j, g, accA, accB);
#pragma unroll
        for (int m = 0; m < 16; m++) {
            int n = nbase + g + 2 * m;
            if (n < N_NODES) {
                out_sc[(size_t)n * 512 + j] = accA[m] * INV_SQRT_C;
                g_up_s[n * 128 + j]         = accB[m] * INV_SQRT_C;
            }
        }
    }
    {
        int jd = t & 63;
        int gd = t >> 6;
        float acc[8];
#pragma unroll
        for (int m = 0; m < 8; m++) acc[m] = 0.f;
        for (int k = 0; k < 128; k += 4) {
            float w0 = W_down[(k + 0) * 64 + jd];
            float w1 = W_down[(k + 1) * 64 + jd];
            float w2 = W_down[(k + 2) * 64 + jd];
            float w3 = W_down[(k + 3) * 64 + jd];
#pragma unroll
            for (int m = 0; m < 8; m++) {
                float4 x = *(const float4*)(s + (gd + 4 * m) * 128 + k);
                acc[m] = fmaf(x.x, w0, acc[m]);
                acc[m] = fmaf(x.y, w1, acc[m]);
                acc[m] = fmaf(x.z, w2, acc[m]);
                acc[m] = fmaf(x.w, w3, acc[m]);
            }
        }
#pragma unroll
        for (int m = 0; m < 8; m++) {
            int n = nbase + gd + 4 * m;
            if (n < N_NODES) g_down[n * 64 + jd] = acc[m] * INV_SQRT_C;
        }
    }
    for (int c = 0; c < 3; c++) {
        const float* vp = v + c * (32 * 128);
        float accA[16], accB[16];
        dual_gemv_128(vp, W_skip1, W_up1, j, g, accA, accB);
#pragma unroll
        for (int m = 0; m < 16; m++) {
            int n = nbase + g + 2 * m;
            if (n < N_NODES) {
                out_sc[(size_t)n * 512 + 128 + j * 3 + c] = accA[m] * INV_SQRT_C;
                g_up_v[n * 384 + c * 128 + j]             = accB[m] * INV_SQRT_C;
            }
        }
    }
}

// ---------------- HMMA edge kernel ------------------------------------------
// 64 edges/CTA, 256 threads (8 warps).  Fragment-major smem layouts:
//   A frag (hi/lo): b32 index ((mb*16 + kb)*32 + lane)*4 + reg      (32 KB each)
//   W frag (hi/lo): b32 index ((kbl*32 + nt)*32 + lane)*2 + reg     (32 KB each)
// m16n8k16 mapping: A a0..a3 = (r, k0-7),(r+8,k0-7),(r,k8-15),(r+8,k8-15)
//                   with r = lane/4, k = (lane%4)*2 +{0,1} within the half.
//                   B b0,b1 = k halves; k=(lane%4)*2+{0,1}, n=lane/4.
//                   D c0..c3 = (r, n0+{0,1}), (r+8, n0+{0,1}), n0=(lane%4)*2.
#define SM_SIDX    0
#define SM_RIDX    256
#define SM_EATTR   512
#define A_HI_OFF   2048
#define A_LO_OFF   34816
#define W_HI_OFF   67584
#define W_LO_OFF   100352
#define EDGE_SMEM_TOTAL 133120

__device__ __forceinline__ void split_f16(float v, __half& hi, __half& lo) {
    hi = __float2half_rn(v);
    lo = __float2half_rn(v - __half2float(hi));
}

// stage weight chunk [kb0, kb0+nkb) x 256 cols into fragment-major W_HI/W_LO
__device__ void stage_W(char* smem, const float* __restrict__ W, int Krows,
                        int ldw, int colbase, int kb0, int nkb)
{
    const int t = threadIdx.x;
    const int total = nkb * 4096;           // 16 k x 256 n per kb
    for (int idx = t; idx < total; idx += 256) {
        int kbl = idx >> 12;
        int kr  = (idx >> 8) & 15;
        int n   = idx & 255;
        int k   = (kb0 + kbl) * 16 + kr;
        float w = (k < Krows) ? W[(size_t)k * ldw + colbase + n] : 0.f;
        __half hi, lo; split_f16(w, hi, lo);
        int nt = n >> 3, nr = n & 7;
        int lane = nr * 4 + ((kr & 7) >> 1);
        int reg  = kr >> 3;
        int b32i = ((kbl * 32 + nt) * 32 + lane) * 2 + reg;
        int hsel = kr & 1;
        *(__half*)(smem + W_HI_OFF + b32i * 4 + hsel * 2) = hi;
        *(__half*)(smem + W_LO_OFF + b32i * 4 + hsel * 2) = lo;
    }
}

// one GEMM layer into acc[16][4]: all warps, N=256 slice per warp
__device__ void layer_mma(char* smem, const float* __restrict__ W, int Krows,
                          int Kblocks, int ldw, int colbase, float acc[16][4])
{
    const int t = threadIdx.x, lane = t & 31, w = t >> 5;
#pragma unroll
    for (int i = 0; i < 16; i++) {
        acc[i][0] = 0.f; acc[i][1] = 0.f; acc[i][2] = 0.f; acc[i][3] = 0.f;
    }
    for (int kb0 = 0; kb0 < Kblocks; kb0 += 4) {
        int nkb = Kblocks - kb0; if (nkb > 4) nkb = 4;
        __syncthreads();
        stage_W(smem, W, Krows, ldw, colbase, kb0, nkb);
        __syncthreads();
        for (int kbl = 0; kbl < nkb; kbl++) {
            int kb = kb0 + kbl;
            uint32_t ah[4][4], al[4][4];
#pragma unroll
            for (int mb = 0; mb < 4; mb++) {
                int ai = ((mb * 16 + kb) * 32 + lane) * 4;
                *(uint4*)ah[mb] = *(const uint4*)(smem + A_HI_OFF + ai * 4);
                *(uint4*)al[mb] = *(const uint4*)(smem + A_LO_OFF + ai * 4);
            }
#pragma unroll
            for (int ntl = 0; ntl < 4; ntl++) {
                int wi = ((kbl * 32 + (w * 4 + ntl)) * 32 + lane) * 2;
                uint32_t bh[2], bl[2];
                *(uint2*)bh = *(const uint2*)(smem + W_HI_OFF + wi * 4);
                *(uint2*)bl = *(const uint2*)(smem + W_LO_OFF + wi * 4);
                // term-major: 4 independent accumulators between dependent reuses
#pragma unroll
                for (int mb = 0; mb < 4; mb++) mma16816(acc[mb * 4 + ntl], ah[mb], bh);
#pragma unroll
                for (int mb = 0; mb < 4; mb++) mma16816(acc[mb * 4 + ntl], ah[mb], bl);
#pragma unroll
                for (int mb = 0; mb < 4; mb++) mma16816(acc[mb * 4 + ntl], al[mb], bh);
            }
        }
    }
    __syncthreads();   // all MMA reads of A/W done before caller overwrites
}

// epilogue: silu(acc*scale) -> next-layer A fragments (hi/lo)
__device__ void epi_silu_frag(char* smem, float acc[16][4], float scale)
{
    const int t = threadIdx.x, lane = t & 31, w = t >> 5;
    uint32_t* ahi = (uint32_t*)(smem + A_HI_OFF);
    uint32_t* alo = (uint32_t*)(smem + A_LO_OFF);
#pragma unroll
    for (int mb = 0; mb < 4; mb++) {
#pragma unroll
        for (int ntl = 0; ntl < 4; ntl++) {
            float* c = acc[mb * 4 + ntl];
            int nt = w * 4 + ntl;
            int kb = nt >> 1;
            int regb = (nt & 1) * 2;
            float y0 = act_silu(c[0], scale), y1 = act_silu(c[1], scale);
            float y2 = act_silu(c[2], scale), y3 = act_silu(c[3], scale);
            __half h0, l0, h1, l1, h2, l2, h3, l3;
            split_f16(y0, h0, l0); split_f16(y1, h1, l1);
            split_f16(y2, h2, l2); split_f16(y3, h3, l3);
            int ai = ((mb * 16 + kb) * 32 + lane) * 4 + regb;
            ahi[ai]     = pack_half2(h0, h1);
            ahi[ai + 1] = pack_half2(h2, h3);
            alo[ai]     = pack_half2(l0, l1);
            alo[ai + 1] = pack_half2(l2, l3);
        }
    }
    __syncthreads();
}

// final epilogue: acc*scale -> f32 dbuf [64][256] (reuses W region)
__device__ void epi_dbuf(char* smem, float acc[16][4], float scale)
{
    float* dbuf = (float*)(smem + W_HI_OFF);
    const int t = threadIdx.x, lane = t & 31, w = t >> 5;
#pragma unroll
    for (int mb = 0; mb < 4; mb++) {
#pragma unroll
        for (int ntl = 0; ntl < 4; ntl++) {
            float* c = acc[mb * 4 + ntl];
            int nt = w * 4 + ntl;
            int r = lane >> 2;
            int n = nt * 8 + (lane & 3) * 2;
            int e = mb * 16 + r;
            *(float2*)(dbuf + (size_t)e * 256 + n)       = make_float2(c[0] * scale, c[1] * scale);
            *(float2*)(dbuf + (size_t)(e + 8) * 256 + n) = make_float2(c[2] * scale, c[3] * scale);
        }
    }
    __syncthreads();
}

__global__ __launch_bounds__(256, 1) void edge_kernel_mma(
    const float* __restrict__ edge_attrs,
    const float* __restrict__ edge_feats,
    const int* __restrict__ edge_index,
    const float* __restrict__ Wm0, const float* __restrict__ Wm1,
    const float* __restrict__ Wm2, const float* __restrict__ Wm3)
{
    extern __shared__ char smem[];
    const int t = threadIdx.x;
    const int ebase = blockIdx.x * 64;

    int*   sidx  = (int*)(smem + SM_SIDX);
    int*   ridx  = (int*)(smem + SM_RIDX);
    float* eattr = (float*)(smem + SM_EATTR);
    if (t < 64) {
        sidx[t] = edge_index[(size_t)(ebase + t) * 2];
        ridx[t] = edge_index[(size_t)(ebase + t) * 2 + 1];
    }
    eattr[t] = edge_attrs[(size_t)ebase * 4 + t];   // 64*4 = 256 = blockDim
    __syncthreads();

    // ---- stage aug (K = 136 padded to 144) into A fragments ----
    {
        const int e = t & 63, h = t >> 6;
        const int mb = e >> 4, r = e & 15;
        const int snd = sidx[e], rcv = ridx[e];
        for (int f = h * 36; f < h * 36 + 36; f++) {
            float val;
            if (f < 8)        val = edge_feats[(size_t)(ebase + e) * 8 + f];
            else if (f < 72)  val = g_down[snd * 64 + (f - 8)];
            else if (f < 136) val = g_down[rcv * 64 + (f - 72)];
            else              val = 0.f;
            __half hi, lo; split_f16(val, hi, lo);
            int kb = f >> 4, kr = f & 15;
            int lane = (r & 7) * 4 + ((kr & 7) >> 1);
            int reg  = (r >> 3) + 2 * (kr >> 3);
            int hsel = kr & 1;
            int ai = ((mb * 16 + kb) * 32 + lane) * 4 + reg;
            *(__half*)(smem + A_HI_OFF + ai * 4 + hsel * 2) = hi;
            *(__half*)(smem + A_LO_OFF + ai * 4 + hsel * 2) = lo;
        }
    }

    float acc[16][4];
    layer_mma(smem, Wm0, 136, 9,  256, 0, acc);
    epi_silu_frag(smem, acc, INV_SQRT_AUG);
    layer_mma(smem, Wm1, 256, 16, 256, 0, acc);
    epi_silu_frag(smem, acc, SIXTEENTH);
    layer_mma(smem, Wm2, 256, 16, 256, 0, acc);
    epi_silu_frag(smem, acc, SIXTEENTH);

    // ---- final layer: two N=256 passes; TP + scatter after each ----
    float* dbuf = (float*)(smem + W_HI_OFF);
#pragma unroll 1
    for (int p = 0; p < 2; p++) {
        layer_mma(smem, Wm3, 256, 16, 512, p * 256, acc);
        epi_dbuf(smem, acc, SIXTEENTH);

        const int j = t & 127;
        const int grp = t >> 7;
#pragma unroll 1
        for (int e = grp * 32; e < grp * 32 + 32; e++) {
            int snd = sidx[e];
            int rcv = ridx[e];
            float y0  = eattr[e * 4 + 0];
            float yv0 = eattr[e * 4 + 1];
            float yv1 = eattr[e * 4 + 2];
            float yv2 = eattr[e * 4 + 3];
            float wA = dbuf[(size_t)e * 256 + j];         // p=0: w1, p=1: w3
            float wB = dbuf[(size_t)e * 256 + 128 + j];   // p=0: w2, p=1: w4
            float xs  = g_up_s[snd * 128 + j];
            float xv0 = g_up_v[snd * 384 + j];
            float xv1 = g_up_v[snd * 384 + 128 + j];
            float xv2 = g_up_v[snd * 384 + 256 + j];
            float* m0r = g_m0 + (size_t)rcv * 256;
            float* m1r = g_m1 + (size_t)rcv * 768;
            if (p == 0) {
                atomicAdd(m0r + j, wA * xs * y0);                 // out0a
                float w2xs = wB * xs;                              // out1a
                atomicAdd(m1r +   0 + j, w2xs * yv0);
                atomicAdd(m1r + 256 + j, w2xs * yv1);
                atomicAdd(m1r + 512 + j, w2xs * yv2);
            } else {
                float dotxy = xv0 * yv0 + xv1 * yv1 + xv2 * yv2;
                atomicAdd(m0r + 128 + j, wB * dotxy * INV_SQRT3); // out0b
                float w3y0 = wA * y0;                              // out1b
                atomicAdd(m1r + 128 + j, w3y0 * xv0);
                atomicAdd(m1r + 384 + j, w3y0 * xv1);
                atomicAdd(m1r + 640 + j, w3y0 * xv2);
            }
        }
        __syncthreads();
    }
}

// ---------------- node post-pass (unchanged) --------------------------------
__global__ __launch_bounds__(256, 2) void node_post_kernel(
    const float* __restrict__ W_lin0,
    const float* __restrict__ W_lin1,
    float* __restrict__ out)
{
    __shared__ float tile[32 * 256];
    const int nbase = blockIdx.x * 32;
    const int t = threadIdx.x;
    const int j = t & 127;
    const int g = t >> 7;

    for (int idx = t; idx < 32 * 256; idx += 256) {
        int nl = idx >> 8;
        int k  = idx & 255;
        int n  = nbase + nl;
        tile[idx] = (n < N_NODES) ? g_m0[(size_t)n * 256 + k] : 0.f;
    }
    __syncthreads();
    {
        float acc[16];
#pragma unroll
        for (int m = 0; m < 16; m++) acc[m] = 0.f;
        for (int k = 0; k < 256; k += 4) {
            float w0 = W_lin0[(k + 0) * 128 + j];
            float w1 = W_lin0[(k + 1) * 128 + j];
            float w2 = W_lin0[(k + 2) * 128 + j];
            float w3 = W_lin0[(k + 3) * 128 + j];
#pragma unroll
            for (int m = 0; m < 16; m++) {
                float4 x = *(const float4*)(tile + (g + 2 * m) * 256 + k);
                acc[m] = fmaf(x.x, w0, acc[m]);
                acc[m] = fmaf(x.y, w1, acc[m]);
                acc[m] = fmaf(x.z, w2, acc[m]);
                acc[m] = fmaf(x.w, w3, acc[m]);
            }
        }
#pragma unroll
        for (int m = 0; m < 16; m++) {
            int n = nbase + g + 2 * m;
            if (n < N_NODES) out[(size_t)n * 512 + j * 4 + 0] = acc[m] * FINAL_SCALE;
        }
    }
    for (int c = 0; c < 3; c++) {
        __syncthreads();
        for (int idx = t; idx < 32 * 256; idx += 256) {
            int nl = idx >> 8;
            int k  = idx & 255;
            int n  = nbase + nl;
            tile[idx] = (n < N_NODES) ? g_m1[(size_t)n * 768 + c * 256 + k] : 0.f;
        }
        __syncthreads();
        float acc[16];
#pragma unroll
        for (int m = 0; m < 16; m++) acc[m] = 0.f;
        for (int k = 0; k < 256; k += 4) {
            float w0 = W_lin1[(k + 0) * 128 + j];
            float w1 = W_lin1[(k + 1) * 128 + j];
            float w2 = W_lin1[(k + 2) * 128 + j];
            float w3 = W_lin1[(k + 3) * 128 + j];
#pragma unroll
            for (int m = 0; m < 16; m++) {
                float4 x = *(const float4*)(tile + (g + 2 * m) * 256 + k);
                acc[m] = fmaf(x.x, w0, acc[m]);
                acc[m] = fmaf(x.y, w1, acc[m]);
                acc[m] = fmaf(x.z, w2, acc[m]);
                acc[m] = fmaf(x.w, w3, acc[m]);
            }
        }
#pragma unroll
        for (int m = 0; m < 16; m++) {
            int n = nbase + g + 2 * m;
            if (n < N_NODES) out[(size_t)n * 512 + j * 4 + 1 + c] = acc[m] * FINAL_SCALE;
        }
    }
}

// ---------------- launch -----------------------------------------------------
extern "C" void kernel_launch(void* const* d_in, const int* in_sizes, int n_in,
                              void* d_out, int out_size)
{
    (void)in_sizes; (void)n_in; (void)out_size;
    const float* node_feats = (const float*)d_in[1];
    const float* edge_attrs = (const float*)d_in[2];
    const float* edge_feats = (const float*)d_in[3];
    const int*   edge_index = (const int*)d_in[4];
    const float* W_up0   = (const float*)d_in[5];
    const float* W_up1   = (const float*)d_in[6];
    const float* W_down  = (const float*)d_in[7];
    const float* Wm0     = (const float*)d_in[8];
    const float* Wm1     = (const float*)d_in[9];
    const float* Wm2     = (const float*)d_in[10];
    const float* Wm3     = (const float*)d_in[11];
    const float* W_lin0  = (const float*)d_in[12];
    const float* W_lin1  = (const float*)d_in[13];
    const float* W_skip0 = (const float*)d_in[14];
    const float* W_skip1 = (const float*)d_in[15];

    float* out    = (float*)d_out;
    float* out_sc = out + (size_t)N_NODES * 512;

    cudaFuncSetAttribute(node_pre_kernel,
                         cudaFuncAttributeMaxDynamicSharedMemorySize, 64 * 1024);
    cudaFuncSetAttribute(edge_kernel_mma,
                         cudaFuncAttributeMaxDynamicSharedMemorySize, EDGE_SMEM_TOTAL);

    zero_kernel<<<512, 256>>>();
    node_pre_kernel<<<(N_NODES + 31) / 32, 256, 64 * 1024>>>(
        node_feats, W_up0, W_up1, W_down, W_skip0, W_skip1, out_sc);
    edge_kernel_mma<<<N_EDGES / 64, 256, EDGE_SMEM_TOTAL>>>(
        edge_attrs, edge_feats, edge_index, Wm0, Wm1, Wm2, Wm3);
    node_post_kernel<<<(N_NODES + 31) / 32, 256>>>(W_lin0, W_lin1, out);
}

// round 14
// speedup vs baseline: 2.0844x; 2.0559x over previous
#include <cuda_runtime.h>
#include <cuda_fp16.h>
#include <cstdint>

#define N_NODES 10000
#define N_EDGES 160000

static __device__ float g_up_s[N_NODES * 128];
static __device__ float g_up_v[N_NODES * 384];
static __device__ float g_down[N_NODES * 64];
static __device__ float g_m0[N_NODES * 256];
static __device__ float g_m1[N_NODES * 768];

// fragment-major fp16 2-split weights: 73 k-chunks x 32 n-tiles x 32 lanes
static __device__ uint2 g_wf_hi[73 * 1024];
static __device__ uint2 g_wf_lo[73 * 1024];

#define INV_SQRT_C   0.08838834764831845f
#define INV_SQRT_AUG 0.08574929257125442f
#define SIXTEENTH    0.0625f
#define INV_SQRT3    0.5773502691896258f
#define FINAL_SCALE  0.00390625f

__device__ __forceinline__ float act_silu(float a, float scale) {
    float y = a * scale;
    return y / (1.0f + __expf(-y));
}

// ---------------- HMMA m16n8k16 fp16 -> fp32 --------------------------------
__device__ __forceinline__ void mma16816(float* c, const uint32_t* a, const uint32_t* b) {
    asm volatile(
        "mma.sync.aligned.m16n8k16.row.col.f32.f16.f16.f32 "
        "{%0,%1,%2,%3},{%4,%5,%6,%7},{%8,%9},{%0,%1,%2,%3};"
        : "+f"(c[0]), "+f"(c[1]), "+f"(c[2]), "+f"(c[3])
        : "r"(a[0]), "r"(a[1]), "r"(a[2]), "r"(a[3]), "r"(b[0]), "r"(b[1]));
}

__device__ __forceinline__ uint32_t pack_half2(__half a, __half b) {
    __half2 h = __halves2half2(a, b);
    return *reinterpret_cast<uint32_t*>(&h);
}

__device__ __forceinline__ void split_f16(float v, __half& hi, __half& lo) {
    hi = __float2half_rn(v);
    lo = __float2half_rn(v - __half2float(hi));
}

// ---------------- zero scratch ----------------------------------------------
__global__ void zero_kernel() {
    float4 z = make_float4(0.f, 0.f, 0.f, 0.f);
    float4* p0 = (float4*)g_m0;
    float4* p1 = (float4*)g_m1;
    const int n0 = N_NODES * 256 / 4;
    const int n1 = N_NODES * 768 / 4;
    int idx = blockIdx.x * blockDim.x + threadIdx.x;
    int stride = gridDim.x * blockDim.x;
    for (int k = idx; k < n0; k += stride) p0[k] = z;
    for (int k = idx; k < n1; k += stride) p1[k] = z;
}

// ---------------- weight prep: fp32 -> fragment-major fp16 hi/lo ------------
// chunk map: [0,9)=Wm0 K136  [9,25)=Wm1  [25,41)=Wm2
//            [41,57)=Wm3 cols 0-255  [57,73)=Wm3 cols 256-511
__global__ void wprep_kernel(const float* __restrict__ Wm0,
                             const float* __restrict__ Wm1,
                             const float* __restrict__ Wm2,
                             const float* __restrict__ Wm3)
{
    int id = blockIdx.x * blockDim.x + threadIdx.x;
    if (id >= 73 * 1024) return;
    int c = id >> 10, pos = id & 1023;
    int nt = pos >> 5, lane = pos & 31;
    const float* W; int Krows, ldw, colbase, kb;
    if (c < 9)       { W = Wm0; Krows = 136; ldw = 256; colbase = 0;   kb = c; }
    else if (c < 25) { W = Wm1; Krows = 256; ldw = 256; colbase = 0;   kb = c - 9; }
    else if (c < 41) { W = Wm2; Krows = 256; ldw = 256; colbase = 0;   kb = c - 25; }
    else if (c < 57) { W = Wm3; Krows = 256; ldw = 512; colbase = 0;   kb = c - 41; }
    else             { W = Wm3; Krows = 256; ldw = 512; colbase = 256; kb = c - 57; }
    int n  = colbase + nt * 8 + (lane >> 2);
    int k0 = kb * 16 + (lane & 3) * 2;
    float wv[4];
#pragma unroll
    for (int r = 0; r < 2; r++)
#pragma unroll
        for (int h = 0; h < 2; h++) {
            int k = k0 + r * 8 + h;
            wv[r * 2 + h] = (k < Krows) ? W[(size_t)k * ldw + n] : 0.f;
        }
    __half h0, l0, h1, l1, h2, l2, h3, l3;
    split_f16(wv[0], h0, l0); split_f16(wv[1], h1, l1);
    split_f16(wv[2], h2, l2); split_f16(wv[3], h3, l3);
    uint2 hi, lo;
    hi.x = pack_half2(h0, h1); hi.y = pack_half2(h2, h3);
    lo.x = pack_half2(l0, l1); lo.y = pack_half2(l2, l3);
    g_wf_hi[id] = hi;
    g_wf_lo[id] = lo;
}

// ---------------- node pre-pass (unchanged FFMA path) -----------------------
__device__ __forceinline__ void dual_gemv_128(const float* __restrict__ Xs,
                                              const float* __restrict__ WA,
                                              const float* __restrict__ WB,
                                              int j, int g,
                                              float* accA, float* accB)
{
#pragma unroll
    for (int m = 0; m < 16; m++) { accA[m] = 0.f; accB[m] = 0.f; }
    for (int k = 0; k < 128; k += 4) {
        float a0 = WA[(k + 0) * 128 + j];
        float a1 = WA[(k + 1) * 128 + j];
        float a2 = WA[(k + 2) * 128 + j];
        float a3 = WA[(k + 3) * 128 + j];
        float b0 = WB[(k + 0) * 128 + j];
        float b1 = WB[(k + 1) * 128 + j];
        float b2 = WB[(k + 2) * 128 + j];
        float b3 = WB[(k + 3) * 128 + j];
#pragma unroll
        for (int m = 0; m < 16; m++) {
            float4 x = *(const float4*)(Xs + (g + 2 * m) * 128 + k);
            accA[m] = fmaf(x.x, a0, accA[m]);
            accA[m] = fmaf(x.y, a1, accA[m]);
            accA[m] = fmaf(x.z, a2, accA[m]);
            accA[m] = fmaf(x.w, a3, accA[m]);
            accB[m] = fmaf(x.x, b0, accB[m]);
            accB[m] = fmaf(x.y, b1, accB[m]);
            accB[m] = fmaf(x.z, b2, accB[m]);
            accB[m] = fmaf(x.w, b3, accB[m]);
        }
    }
}

__global__ __launch_bounds__(256, 1) void node_pre_kernel(
    const float* __restrict__ node_feats,
    const float* __restrict__ W_up0, const float* __restrict__ W_up1,
    const float* __restrict__ W_down,
    const float* __restrict__ W_skip0, const float* __restrict__ W_skip1,
    float* __restrict__ out_sc)
{
    extern __shared__ float sm[];
    float* s = sm;
    float* v = sm + 32 * 128;
    const int nbase = blockIdx.x * 32;
    const int t = threadIdx.x;

    for (int idx = t; idx < 32 * 512; idx += 256) {
        int nl = idx >> 9;
        int f  = idx & 511;
        int n  = nbase + nl;
        float val = (n < N_NODES) ? node_feats[(size_t)n * 512 + f] : 0.f;
        if (f < 128) {
            s[nl * 128 + f] = val;
        } else {
            int r = f - 128;
            int i = r / 3;
            int c = r - 3 * i;
            v[c * (32 * 128) + nl * 128 + i] = val;
        }
    }
    __syncthreads();

    const int j = t & 127;
    const int g = t >> 7;
    {
        float accA[16], accB[16];
        dual_gemv_128(s, W_skip0, W_up0, j, g, accA, accB);
#pragma unroll
        for (int m = 0; m < 16; m++) {
            int n = nbase + g + 2 * m;
            if (n < N_NODES) {
                out_sc[(size_t)n * 512 + j] = accA[m] * INV_SQRT_C;
                g_up_s[n * 128 + j]         = accB[m] * INV_SQRT_C;
            }
        }
    }
    {
        int jd = t & 63;
        int gd = t >> 6;
        float acc[8];
#pragma unroll
        for (int m = 0; m < 8; m++) acc[m] = 0.f;
        for (int k = 0; k < 128; k += 4) {
            float w0 = W_down[(k + 0) * 64 + jd];
            float w1 = W_down[(k + 1) * 64 + jd];
            float w2 = W_down[(k + 2) * 64 + jd];
            float w3 = W_down[(k + 3) * 64 + jd];
#pragma unroll
            for (int m = 0; m < 8; m++) {
                float4 x = *(const float4*)(s + (gd + 4 * m) * 128 + k);
                acc[m] = fmaf(x.x, w0, acc[m]);
                acc[m] = fmaf(x.y, w1, acc[m]);
                acc[m] = fmaf(x.z, w2, acc[m]);
                acc[m] = fmaf(x.w, w3, acc[m]);
            }
        }
#pragma unroll
        for (int m = 0; m < 8; m++) {
            int n = nbase + gd + 4 * m;
            if (n < N_NODES) g_down[n * 64 + jd] = acc[m] * INV_SQRT_C;
        }
    }
    for (int c = 0; c < 3; c++) {
        const float* vp = v + c * (32 * 128);
        float accA[16], accB[16];
        dual_gemv_128(vp, W_skip1, W_up1, j, g, accA, accB);
#pragma unroll
        for (int m = 0; m < 16; m++) {
            int n = nbase + g + 2 * m;
            if (n < N_NODES) {
                out_sc[(size_t)n * 512 + 128 + j * 3 + c] = accA[m] * INV_SQRT_C;
                g_up_v[n * 384 + c * 128 + j]             = accB[m] * INV_SQRT_C;
            }
        }
    }
}

// ---------------- HMMA edge kernel (weights from global fragments) ----------
// 64 edges/CTA, 256 threads (8 warps).
//   A frag (hi/lo): b32 index ((mb*16 + kb)*32 + lane)*4 + reg      (32 KB each)
//   B frag: g_wf_hi/lo[((cstart+kbl)*32 + nt)*32 + lane]  (uint2 = b0,b1)
#define SM_SIDX    0
#define SM_RIDX    256
#define SM_EATTR   512
#define A_HI_OFF   2048
#define A_LO_OFF   34816
#define DBUF_OFF   67584
#define EDGE_SMEM_TOTAL 133120

// one GEMM layer into acc[16][4]; no smem writes, B streamed from L2
__device__ void layer_mma2(char* smem, int cstart, int Kblocks, float acc[16][4])
{
    const int t = threadIdx.x, lane = t & 31, w = t >> 5;
#pragma unroll
    for (int i = 0; i < 16; i++) {
        acc[i][0] = 0.f; acc[i][1] = 0.f; acc[i][2] = 0.f; acc[i][3] = 0.f;
    }
    const int bbase = (cstart * 32 + w * 4) * 32 + lane;
    uint2 bh[4], bl[4];
#pragma unroll
    for (int ntl = 0; ntl < 4; ntl++) {
        bh[ntl] = g_wf_hi[bbase + ntl * 32];
        bl[ntl] = g_wf_lo[bbase + ntl * 32];
    }
#pragma unroll 1
    for (int kbl = 0; kbl < Kblocks; kbl++) {
        uint32_t ah[4][4], al[4][4];
#pragma unroll
        for (int mb = 0; mb < 4; mb++) {
            int ai = ((mb * 16 + kbl) * 32 + lane) * 4;
            *(uint4*)ah[mb] = *(const uint4*)(smem + A_HI_OFF + ai * 4);
            *(uint4*)al[mb] = *(const uint4*)(smem + A_LO_OFF + ai * 4);
        }
        uint2 nbh[4], nbl[4];
        if (kbl + 1 < Kblocks) {
            int nb = bbase + (kbl + 1) * 1024;
#pragma unroll
            for (int ntl = 0; ntl < 4; ntl++) {
                nbh[ntl] = g_wf_hi[nb + ntl * 32];
                nbl[ntl] = g_wf_lo[nb + ntl * 32];
            }
        }
#pragma unroll
        for (int ntl = 0; ntl < 4; ntl++) {
            uint32_t bhh[2] = { bh[ntl].x, bh[ntl].y };
            uint32_t bll[2] = { bl[ntl].x, bl[ntl].y };
            // term-major: 4 independent accumulators between dependent reuses
#pragma unroll
            for (int mb = 0; mb < 4; mb++) mma16816(acc[mb * 4 + ntl], ah[mb], bhh);
#pragma unroll
            for (int mb = 0; mb < 4; mb++) mma16816(acc[mb * 4 + ntl], ah[mb], bll);
#pragma unroll
            for (int mb = 0; mb < 4; mb++) mma16816(acc[mb * 4 + ntl], al[mb], bhh);
        }
#pragma unroll
        for (int ntl = 0; ntl < 4; ntl++) { bh[ntl] = nbh[ntl]; bl[ntl] = nbl[ntl]; }
    }
}

// epilogue: silu(acc*scale) -> next-layer A fragments (hi/lo)
// caller must __syncthreads() before (A frags still being read by layer_mma2)
__device__ void epi_silu_frag(char* smem, float acc[16][4], float scale)
{
    const int t = threadIdx.x, lane = t & 31, w = t >> 5;
    uint32_t* ahi = (uint32_t*)(smem + A_HI_OFF);
    uint32_t* alo = (uint32_t*)(smem + A_LO_OFF);
#pragma unroll
    for (int mb = 0; mb < 4; mb++) {
#pragma unroll
        for (int ntl = 0; ntl < 4; ntl++) {
            float* c = acc[mb * 4 + ntl];
            int nt = w * 4 + ntl;
            int kb = nt >> 1;
            int regb = (nt & 1) * 2;
            float y0 = act_silu(c[0], scale), y1 = act_silu(c[1], scale);
            float y2 = act_silu(c[2], scale), y3 = act_silu(c[3], scale);
            __half h0, l0, h1, l1, h2, l2, h3, l3;
            split_f16(y0, h0, l0); split_f16(y1, h1, l1);
            split_f16(y2, h2, l2); split_f16(y3, h3, l3);
            int ai = ((mb * 16 + kb) * 32 + lane) * 4 + regb;
            ahi[ai]     = pack_half2(h0, h1);
            ahi[ai + 1] = pack_half2(h2, h3);
            alo[ai]     = pack_half2(l0, l1);
            alo[ai + 1] = pack_half2(l2, l3);
        }
    }
    __syncthreads();
}

// final epilogue: acc*scale -> f32 dbuf [64][256]
__device__ void epi_dbuf(char* smem, float acc[16][4], float scale)
{
    float* dbuf = (float*)(smem + DBUF_OFF);
    const int t = threadIdx.x, lane = t & 31, w = t >> 5;
#pragma unroll
    for (int mb = 0; mb < 4; mb++) {
#pragma unroll
        for (int ntl = 0; ntl < 4; ntl++) {
            float* c = acc[mb * 4 + ntl];
            int nt = w * 4 + ntl;
            int r = lane >> 2;
            int n = nt * 8 + (lane & 3) * 2;
            int e = mb * 16 + r;
            *(float2*)(dbuf + (size_t)e * 256 + n)       = make_float2(c[0] * scale, c[1] * scale);
            *(float2*)(dbuf + (size_t)(e + 8) * 256 + n) = make_float2(c[2] * scale, c[3] * scale);
        }
    }
    __syncthreads();
}

__global__ __launch_bounds__(256, 1) void edge_kernel_mma(
    const float* __restrict__ edge_attrs,
    const float* __restrict__ edge_feats,
    const int* __restrict__ edge_index)
{
    extern __shared__ char smem[];
    const int t = threadIdx.x;
    const int ebase = blockIdx.x * 64;

    int*   sidx  = (int*)(smem + SM_SIDX);
    int*   ridx  = (int*)(smem + SM_RIDX);
    float* eattr = (float*)(smem + SM_EATTR);
    if (t < 64) {
        sidx[t] = edge_index[(size_t)(ebase + t) * 2];
        ridx[t] = edge_index[(size_t)(ebase + t) * 2 + 1];
    }
    eattr[t] = edge_attrs[(size_t)ebase * 4 + t];   // 64*4 = 256 = blockDim
    __syncthreads();

    // ---- stage aug (K = 136 padded to 144) into A fragments ----
    {
        const int e = t & 63, h = t >> 6;
        const int mb = e >> 4, r = e & 15;
        const int snd = sidx[e], rcv = ridx[e];
        for (int f = h * 36; f < h * 36 + 36; f++) {
            float val;
            if (f < 8)        val = edge_feats[(size_t)(ebase + e) * 8 + f];
            else if (f < 72)  val = g_down[snd * 64 + (f - 8)];
            else if (f < 136) val = g_down[rcv * 64 + (f - 72)];
            else              val = 0.f;
            __half hi, lo; split_f16(val, hi, lo);
            int kb = f >> 4, kr = f & 15;
            int lane = (r & 7) * 4 + ((kr & 7) >> 1);
            int reg  = (r >> 3) + 2 * (kr >> 3);
            int hsel = kr & 1;
            int ai = ((mb * 16 + kb) * 32 + lane) * 4 + reg;
            *(__half*)(smem + A_HI_OFF + ai * 4 + hsel * 2) = hi;
            *(__half*)(smem + A_LO_OFF + ai * 4 + hsel * 2) = lo;
        }
    }
    __syncthreads();

    float acc[16][4];
    layer_mma2(smem, 0, 9, acc);    // Wm0
    __syncthreads();
    epi_silu_frag(smem, acc, INV_SQRT_AUG);
    layer_mma2(smem, 9, 16, acc);   // Wm1
    __syncthreads();
    epi_silu_frag(smem, acc, SIXTEENTH);
    layer_mma2(smem, 25, 16, acc);  // Wm2
    __syncthreads();
    epi_silu_frag(smem, acc, SIXTEENTH);

    // ---- final layer: two N=256 passes; TP + scatter after each ----
    float* dbuf = (float*)(smem + DBUF_OFF);
#pragma unroll 1
    for (int p = 0; p < 2; p++) {
        layer_mma2(smem, 41 + p * 16, 16, acc);   // Wm3 halves
        __syncthreads();
        epi_dbuf(smem, acc, SIXTEENTH);

        const int j = t & 127;
        const int grp = t >> 7;
#pragma unroll 1
        for (int e = grp * 32; e < grp * 32 + 32; e++) {
            int snd = sidx[e];
            int rcv = ridx[e];
            float y0  = eattr[e * 4 + 0];
            float yv0 = eattr[e * 4 + 1];
            float yv1 = eattr[e * 4 + 2];
            float yv2 = eattr[e * 4 + 3];
            float wA = dbuf[(size_t)e * 256 + j];         // p=0: w1, p=1: w3
            float wB = dbuf[(size_t)e * 256 + 128 + j];   // p=0: w2, p=1: w4
            float xs  = g_up_s[snd * 128 + j];
            float xv0 = g_up_v[snd * 384 + j];
            float xv1 = g_up_v[snd * 384 + 128 + j];
            float xv2 = g_up_v[snd * 384 + 256 + j];
            float* m0r = g_m0 + (size_t)rcv * 256;
            float* m1r = g_m1 + (size_t)rcv * 768;
            if (p == 0) {
                atomicAdd(m0r + j, wA * xs * y0);                 // out0a
                float w2xs = wB * xs;                              // out1a
                atomicAdd(m1r +   0 + j, w2xs * yv0);
                atomicAdd(m1r + 256 + j, w2xs * yv1);
                atomicAdd(m1r + 512 + j, w2xs * yv2);
            } else {
                float dotxy = xv0 * yv0 + xv1 * yv1 + xv2 * yv2;
                atomicAdd(m0r + 128 + j, wB * dotxy * INV_SQRT3); // out0b
                float w3y0 = wA * y0;                              // out1b
                atomicAdd(m1r + 128 + j, w3y0 * xv0);
                atomicAdd(m1r + 384 + j, w3y0 * xv1);
                atomicAdd(m1r + 640 + j, w3y0 * xv2);
            }
        }
        __syncthreads();
    }
}

// ---------------- node post-pass (unchanged) --------------------------------
__global__ __launch_bounds__(256, 2) void node_post_kernel(
    const float* __restrict__ W_lin0,
    const float* __restrict__ W_lin1,
    float* __restrict__ out)
{
    __shared__ float tile[32 * 256];
    const int nbase = blockIdx.x * 32;
    const int t = threadIdx.x;
    const int j = t & 127;
    const int g = t >> 7;

    for (int idx = t; idx < 32 * 256; idx += 256) {
        int nl = idx >> 8;
        int k  = idx & 255;
        int n  = nbase + nl;
        tile[idx] = (n < N_NODES) ? g_m0[(size_t)n * 256 + k] : 0.f;
    }
    __syncthreads();
    {
        float acc[16];
#pragma unroll
        for (int m = 0; m < 16; m++) acc[m] = 0.f;
        for (int k = 0; k < 256; k += 4) {
            float w0 = W_lin0[(k + 0) * 128 + j];
            float w1 = W_lin0[(k + 1) * 128 + j];
            float w2 = W_lin0[(k + 2) * 128 + j];
            float w3 = W_lin0[(k + 3) * 128 + j];
#pragma unroll
            for (int m = 0; m < 16; m++) {
                float4 x = *(const float4*)(tile + (g + 2 * m) * 256 + k);
                acc[m] = fmaf(x.x, w0, acc[m]);
                acc[m] = fmaf(x.y, w1, acc[m]);
                acc[m] = fmaf(x.z, w2, acc[m]);
                acc[m] = fmaf(x.w, w3, acc[m]);
            }
        }
#pragma unroll
        for (int m = 0; m < 16; m++) {
            int n = nbase + g + 2 * m;
            if (n < N_NODES) out[(size_t)n * 512 + j * 4 + 0] = acc[m] * FINAL_SCALE;
        }
    }
    for (int c = 0; c < 3; c++) {
        __syncthreads();
        for (int idx = t; idx < 32 * 256; idx += 256) {
            int nl = idx >> 8;
            int k  = idx & 255;
            int n  = nbase + nl;
            tile[idx] = (n < N_NODES) ? g_m1[(size_t)n * 768 + c * 256 + k] : 0.f;
        }
        __syncthreads();
        float acc[16];
#pragma unroll
        for (int m = 0; m < 16; m++) acc[m] = 0.f;
        for (int k = 0; k < 256; k += 4) {
            float w0 = W_lin1[(k + 0) * 128 + j];
            float w1 = W_lin1[(k + 1) * 128 + j];
            float w2 = W_lin1[(k + 2) * 128 + j];
            float w3 = W_lin1[(k + 3) * 128 + j];
#pragma unroll
            for (int m = 0; m < 16; m++) {
                float4 x = *(const float4*)(tile + (g + 2 * m) * 256 + k);
                acc[m] = fmaf(x.x, w0, acc[m]);
                acc[m] = fmaf(x.y, w1, acc[m]);
                acc[m] = fmaf(x.z, w2, acc[m]);
                acc[m] = fmaf(x.w, w3, acc[m]);
            }
        }
#pragma unroll
        for (int m = 0; m < 16; m++) {
            int n = nbase + g + 2 * m;
            if (n < N_NODES) out[(size_t)n * 512 + j * 4 + 1 + c] = acc[m] * FINAL_SCALE;
        }
    }
}

// ---------------- launch -----------------------------------------------------
extern "C" void kernel_launch(void* const* d_in, const int* in_sizes, int n_in,
                              void* d_out, int out_size)
{
    (void)in_sizes; (void)n_in; (void)out_size;
    const float* node_feats = (const float*)d_in[1];
    const float* edge_attrs = (const float*)d_in[2];
    const float* edge_feats = (const float*)d_in[3];
    const int*   edge_index = (const int*)d_in[4];
    const float* W_up0   = (const float*)d_in[5];
    const float* W_up1   = (const float*)d_in[6];
    const float* W_down  = (const float*)d_in[7];
    const float* Wm0     = (const float*)d_in[8];
    const float* Wm1     = (const float*)d_in[9];
    const float* Wm2     = (const float*)d_in[10];
    const float* Wm3     = (const float*)d_in[11];
    const float* W_lin0  = (const float*)d_in[12];
    const float* W_lin1  = (const float*)d_in[13];
    const float* W_skip0 = (const float*)d_in[14];
    const float* W_skip1 = (const float*)d_in[15];

    float* out    = (float*)d_out;
    float* out_sc = out + (size_t)N_NODES * 512;

    cudaFuncSetAttribute(node_pre_kernel,
                         cudaFuncAttributeMaxDynamicSharedMemorySize, 64 * 1024);
    cudaFuncSetAttribute(edge_kernel_mma,
                         cudaFuncAttributeMaxDynamicSharedMemorySize, EDGE_SMEM_TOTAL);

    zero_kernel<<<512, 256>>>();
    wprep_kernel<<<(73 * 1024 + 255) / 256, 256>>>(Wm0, Wm1, Wm2, Wm3);
    node_pre_kernel<<<(N_NODES + 31) / 32, 256, 64 * 1024>>>(
        node_feats, W_up0, W_up1, W_down, W_skip0, W_skip1, out_sc);
    edge_kernel_mma<<<N_EDGES / 64, 256, EDGE_SMEM_TOTAL>>>(
        edge_attrs, edge_feats, edge_index);
    node_post_kernel<<<(N_NODES + 31) / 32, 256>>>(W_lin0, W_lin1, out);
}

// round 15
// speedup vs baseline: 2.6740x; 1.2829x over previous
#include <cuda_runtime.h>
#include <cuda_fp16.h>
#include <cstdint>

#define N_NODES 10000
#define N_EDGES 160000

static __device__ float g_up_s[N_NODES * 128];
static __device__ float g_up_v[N_NODES * 384];
static __device__ float g_down[N_NODES * 64];
static __device__ float g_m0[N_NODES * 256];
static __device__ float g_m1[N_NODES * 768];

// fragment-major fp16 2-split weights: 73 k-chunks x 32 n-tiles x 32 lanes
static __device__ uint2 g_wf_hi[73 * 1024];
static __device__ uint2 g_wf_lo[73 * 1024];

#define INV_SQRT_C   0.08838834764831845f
#define INV_SQRT_AUG 0.08574929257125442f
#define SIXTEENTH    0.0625f
#define INV_SQRT3    0.5773502691896258f
#define FINAL_SCALE  0.00390625f

__device__ __forceinline__ float act_silu(float a, float scale) {
    float y = a * scale;
    return y / (1.0f + __expf(-y));
}

// ---------------- HMMA m16n8k16 fp16 -> fp32 --------------------------------
__device__ __forceinline__ void mma16816(float* c, const uint32_t* a, const uint32_t* b) {
    asm volatile(
        "mma.sync.aligned.m16n8k16.row.col.f32.f16.f16.f32 "
        "{%0,%1,%2,%3},{%4,%5,%6,%7},{%8,%9},{%0,%1,%2,%3};"
        : "+f"(c[0]), "+f"(c[1]), "+f"(c[2]), "+f"(c[3])
        : "r"(a[0]), "r"(a[1]), "r"(a[2]), "r"(a[3]), "r"(b[0]), "r"(b[1]));
}

__device__ __forceinline__ uint32_t pack_half2(__half a, __half b) {
    __half2 h = __halves2half2(a, b);
    return *reinterpret_cast<uint32_t*>(&h);
}

__device__ __forceinline__ void split_f16(float v, __half& hi, __half& lo) {
    hi = __float2half_rn(v);
    lo = __float2half_rn(v - __half2float(hi));
}

// ---------------- zero scratch ----------------------------------------------
__global__ void zero_kernel() {
    float4 z = make_float4(0.f, 0.f, 0.f, 0.f);
    float4* p0 = (float4*)g_m0;
    float4* p1 = (float4*)g_m1;
    const int n0 = N_NODES * 256 / 4;
    const int n1 = N_NODES * 768 / 4;
    int idx = blockIdx.x * blockDim.x + threadIdx.x;
    int stride = gridDim.x * blockDim.x;
    for (int k = idx; k < n0; k += stride) p0[k] = z;
    for (int k = idx; k < n1; k += stride) p1[k] = z;
}

// ---------------- weight prep: fp32 -> fragment-major fp16 hi/lo ------------
// chunk map: [0,9)=Wm0 K136  [9,25)=Wm1  [25,41)=Wm2
//            [41,57)=Wm3 cols 0-255  [57,73)=Wm3 cols 256-511
// For Wm3 chunks the n-tile slots are PERMUTED so that warp w's 4 slots are
// col-blocks { j, j+8, 128+j, 128+j+8 } with j = w*16 — pairing (j, 128+j)
// inside one thread's accumulators for the register TP epilogue.
__global__ void wprep_kernel(const float* __restrict__ Wm0,
                             const float* __restrict__ Wm1,
                             const float* __restrict__ Wm2,
                             const float* __restrict__ Wm3)
{
    int id = blockIdx.x * blockDim.x + threadIdx.x;
    if (id >= 73 * 1024) return;
    int c = id >> 10, pos = id & 1023;
    int nt = pos >> 5, lane = pos & 31;
    const float* W; int Krows, ldw, colbase, kb;
    bool perm = false;
    if (c < 9)       { W = Wm0; Krows = 136; ldw = 256; colbase = 0;   kb = c; }
    else if (c < 25) { W = Wm1; Krows = 256; ldw = 256; colbase = 0;   kb = c - 9; }
    else if (c < 41) { W = Wm2; Krows = 256; ldw = 256; colbase = 0;   kb = c - 25; }
    else if (c < 57) { W = Wm3; Krows = 256; ldw = 512; colbase = 0;   kb = c - 41; perm = true; }
    else             { W = Wm3; Krows = 256; ldw = 512; colbase = 256; kb = c - 57; perm = true; }
    int ntc = nt;
    if (perm) {
        int w = nt >> 2, s = nt & 3;
        ntc = (s & 2) ? (16 + w * 2 + (s & 1)) : (w * 2 + (s & 1));
    }
    int n  = colbase + ntc * 8 + (lane >> 2);
    int k0 = kb * 16 + (lane & 3) * 2;
    float wv[4];
#pragma unroll
    for (int r = 0; r < 2; r++)
#pragma unroll
        for (int h = 0; h < 2; h++) {
            int k = k0 + r * 8 + h;
            wv[r * 2 + h] = (k < Krows) ? W[(size_t)k * ldw + n] : 0.f;
        }
    __half h0, l0, h1, l1, h2, l2, h3, l3;
    split_f16(wv[0], h0, l0); split_f16(wv[1], h1, l1);
    split_f16(wv[2], h2, l2); split_f16(wv[3], h3, l3);
    uint2 hi, lo;
    hi.x = pack_half2(h0, h1); hi.y = pack_half2(h2, h3);
    lo.x = pack_half2(l0, l1); lo.y = pack_half2(l2, l3);
    g_wf_hi[id] = hi;
    g_wf_lo[id] = lo;
}

// ---------------- node pre-pass (unchanged FFMA path) -----------------------
__device__ __forceinline__ void dual_gemv_128(const float* __restrict__ Xs,
                                              const float* __restrict__ WA,
                                              const float* __restrict__ WB,
                                              int j, int g,
                                              float* accA, float* accB)
{
#pragma unroll
    for (int m = 0; m < 16; m++) { accA[m] = 0.f; accB[m] = 0.f; }
    for (int k = 0; k < 128; k += 4) {
        float a0 = WA[(k + 0) * 128 + j];
        float a1 = WA[(k + 1) * 128 + j];
        float a2 = WA[(k + 2) * 128 + j];
        float a3 = WA[(k + 3) * 128 + j];
        float b0 = WB[(k + 0) * 128 + j];
        float b1 = WB[(k + 1) * 128 + j];
        float b2 = WB[(k + 2) * 128 + j];
        float b3 = WB[(k + 3) * 128 + j];
#pragma unroll
        for (int m = 0; m < 16; m++) {
            float4 x = *(const float4*)(Xs + (g + 2 * m) * 128 + k);
            accA[m] = fmaf(x.x, a0, accA[m]);
            accA[m] = fmaf(x.y, a1, accA[m]);
            accA[m] = fmaf(x.z, a2, accA[m]);
            accA[m] = fmaf(x.w, a3, accA[m]);
            accB[m] = fmaf(x.x, b0, accB[m]);
            accB[m] = fmaf(x.y, b1, accB[m]);
            accB[m] = fmaf(x.z, b2, accB[m]);
            accB[m] = fmaf(x.w, b3, accB[m]);
        }
    }
}

__global__ __launch_bounds__(256, 1) void node_pre_kernel(
    const float* __restrict__ node_feats,
    const float* __restrict__ W_up0, const float* __restrict__ W_up1,
    const float* __restrict__ W_down,
    const float* __restrict__ W_skip0, const float* __restrict__ W_skip1,
    float* __restrict__ out_sc)
{
    extern __shared__ float sm[];
    float* s = sm;
    float* v = sm + 32 * 128;
    const int nbase = blockIdx.x * 32;
    const int t = threadIdx.x;

    for (int idx = t; idx < 32 * 512; idx += 256) {
        int nl = idx >> 9;
        int f  = idx & 511;
        int n  = nbase + nl;
        float val = (n < N_NODES) ? node_feats[(size_t)n * 512 + f] : 0.f;
        if (f < 128) {
            s[nl * 128 + f] = val;
        } else {
            int r = f - 128;
            int i = r / 3;
            int c = r - 3 * i;
            v[c * (32 * 128) + nl * 128 + i] = val;
        }
    }
    __syncthreads();

    const int j = t & 127;
    const int g = t >> 7;
    {
        float accA[16], accB[16];
        dual_gemv_128(s, W_skip0, W_up0, j, g, accA, accB);
#pragma unroll
        for (int m = 0; m < 16; m++) {
            int n = nbase + g + 2 * m;
            if (n < N_NODES) {
                out_sc[(size_t)n * 512 + j] = accA[m] * INV_SQRT_C;
                g_up_s[n * 128 + j]         = accB[m] * INV_SQRT_C;
            }
        }
    }
    {
        int jd = t & 63;
        int gd = t >> 6;
        float acc[8];
#pragma unroll
        for (int m = 0; m < 8; m++) acc[m] = 0.f;
        for (int k = 0; k < 128; k += 4) {
            float w0 = W_down[(k + 0) * 64 + jd];
            float w1 = W_down[(k + 1) * 64 + jd];
            float w2 = W_down[(k + 2) * 64 + jd];
            float w3 = W_down[(k + 3) * 64 + jd];
#pragma unroll
            for (int m = 0; m < 8; m++) {
                float4 x = *(const float4*)(s + (gd + 4 * m) * 128 + k);
                acc[m] = fmaf(x.x, w0, acc[m]);
                acc[m] = fmaf(x.y, w1, acc[m]);
                acc[m] = fmaf(x.z, w2, acc[m]);
                acc[m] = fmaf(x.w, w3, acc[m]);
            }
        }
#pragma unroll
        for (int m = 0; m < 8; m++) {
            int n = nbase + gd + 4 * m;
            if (n < N_NODES) g_down[n * 64 + jd] = acc[m] * INV_SQRT_C;
        }
    }
    for (int c = 0; c < 3; c++) {
        const float* vp = v + c * (32 * 128);
        float accA[16], accB[16];
        dual_gemv_128(vp, W_skip1, W_up1, j, g, accA, accB);
#pragma unroll
        for (int m = 0; m < 16; m++) {
            int n = nbase + g + 2 * m;
            if (n < N_NODES) {
                out_sc[(size_t)n * 512 + 128 + j * 3 + c] = accA[m] * INV_SQRT_C;
                g_up_v[n * 384 + c * 128 + j]             = accB[m] * INV_SQRT_C;
            }
        }
    }
}

// ---------------- HMMA edge kernel (2 CTAs/SM, register TP) -----------------
// 64 edges/CTA, 256 threads (8 warps).
//   A frag (hi/lo): b32 index ((mb*16 + kb)*32 + lane)*4 + reg      (32 KB each)
//   B frag: g_wf_hi/lo[((cstart+kbl)*32 + w*4 + ntl)*32 + lane]
#define SM_SIDX    0
#define SM_RIDX    256
#define SM_EATTR   512
#define A_HI_OFF   2048
#define A_LO_OFF   34816
#define EDGE_SMEM_TOTAL 67584

// one GEMM layer into acc[16][4]; B streamed from L2 with 1-deep prefetch;
// A regs reused between hi and lo passes to stay under 128 regs.
__device__ void layer_mma2(char* smem, int cstart, int Kblocks, float acc[16][4])
{
    const int t = threadIdx.x, lane = t & 31, w = t >> 5;
#pragma unroll
    for (int i = 0; i < 16; i++) {
        acc[i][0] = 0.f; acc[i][1] = 0.f; acc[i][2] = 0.f; acc[i][3] = 0.f;
    }
    const int bbase = (cstart * 32 + w * 4) * 32 + lane;
    uint2 bh[4], bl[4];
#pragma unroll
    for (int ntl = 0; ntl < 4; ntl++) {
        bh[ntl] = g_wf_hi[bbase + ntl * 32];
        bl[ntl] = g_wf_lo[bbase + ntl * 32];
    }
#pragma unroll 1
    for (int kbl = 0; kbl < Kblocks; kbl++) {
        uint32_t av[4][4];
        // prefetch next B early (covers L2 latency under the MMA block)
        uint2 nbh[4], nbl[4];
        if (kbl + 1 < Kblocks) {
            int nb = bbase + (kbl + 1) * 1024;
#pragma unroll
            for (int ntl = 0; ntl < 4; ntl++) {
                nbh[ntl] = g_wf_hi[nb + ntl * 32];
                nbl[ntl] = g_wf_lo[nb + ntl * 32];
            }
        }
        // A_HI pass: hi*w_hi and hi*w_lo
#pragma unroll
        for (int mb = 0; mb < 4; mb++) {
            int ai = ((mb * 16 + kbl) * 32 + lane) * 4;
            *(uint4*)av[mb] = *(const uint4*)(smem + A_HI_OFF + ai * 4);
        }
#pragma unroll
        for (int ntl = 0; ntl < 4; ntl++) {
            uint32_t bhh[2] = { bh[ntl].x, bh[ntl].y };
#pragma unroll
            for (int mb = 0; mb < 4; mb++) mma16816(acc[mb * 4 + ntl], av[mb], bhh);
        }
#pragma unroll
        for (int ntl = 0; ntl < 4; ntl++) {
            uint32_t bll[2] = { bl[ntl].x, bl[ntl].y };
#pragma unroll
            for (int mb = 0; mb < 4; mb++) mma16816(acc[mb * 4 + ntl], av[mb], bll);
        }
        // A_LO pass: lo*w_hi  (reuse av regs)
#pragma unroll
        for (int mb = 0; mb < 4; mb++) {
            int ai = ((mb * 16 + kbl) * 32 + lane) * 4;
            *(uint4*)av[mb] = *(const uint4*)(smem + A_LO_OFF + ai * 4);
        }
#pragma unroll
        for (int ntl = 0; ntl < 4; ntl++) {
            uint32_t bhh[2] = { bh[ntl].x, bh[ntl].y };
#pragma unroll
            for (int mb = 0; mb < 4; mb++) mma16816(acc[mb * 4 + ntl], av[mb], bhh);
        }
#pragma unroll
        for (int ntl = 0; ntl < 4; ntl++) { bh[ntl] = nbh[ntl]; bl[ntl] = nbl[ntl]; }
    }
}

// epilogue: silu(acc*scale) -> next-layer A fragments (hi/lo)
__device__ void epi_silu_frag(char* smem, float acc[16][4], float scale)
{
    const int t = threadIdx.x, lane = t & 31, w = t >> 5;
    uint32_t* ahi = (uint32_t*)(smem + A_HI_OFF);
    uint32_t* alo = (uint32_t*)(smem + A_LO_OFF);
#pragma unroll
    for (int mb = 0; mb < 4; mb++) {
#pragma unroll
        for (int ntl = 0; ntl < 4; ntl++) {
            float* c = acc[mb * 4 + ntl];
            int nt = w * 4 + ntl;
            int kb = nt >> 1;
            int regb = (nt & 1) * 2;
            float y0 = act_silu(c[0], scale), y1 = act_silu(c[1], scale);
            float y2 = act_silu(c[2], scale), y3 = act_silu(c[3], scale);
            __half h0, l0, h1, l1, h2, l2, h3, l3;
            split_f16(y0, h0, l0); split_f16(y1, h1, l1);
            split_f16(y2, h2, l2); split_f16(y3, h3, l3);
            int ai = ((mb * 16 + kb) * 32 + lane) * 4 + regb;
            ahi[ai]     = pack_half2(h0, h1);
            ahi[ai + 1] = pack_half2(h2, h3);
            alo[ai]     = pack_half2(l0, l1);
            alo[ai + 1] = pack_half2(l2, l3);
        }
    }
    __syncthreads();
}

__global__ __launch_bounds__(256, 2) void edge_kernel_mma(
    const float* __restrict__ edge_attrs,
    const float* __restrict__ edge_feats,
    const int* __restrict__ edge_index)
{
    extern __shared__ char smem[];
    const int t = threadIdx.x;
    const int ebase = blockIdx.x * 64;

    int*   sidx  = (int*)(smem + SM_SIDX);
    int*   ridx  = (int*)(smem + SM_RIDX);
    float* eattr = (float*)(smem + SM_EATTR);
    if (t < 64) {
        sidx[t] = edge_index[(size_t)(ebase + t) * 2];
        ridx[t] = edge_index[(size_t)(ebase + t) * 2 + 1];
    }
    eattr[t] = edge_attrs[(size_t)ebase * 4 + t];   // 64*4 = 256 = blockDim
    __syncthreads();

    // ---- stage aug (K = 136 padded to 144) into A fragments ----
    {
        const int e = t & 63, h = t >> 6;
        const int mb = e >> 4, r = e & 15;
        const int snd = sidx[e], rcv = ridx[e];
        for (int f = h * 36; f < h * 36 + 36; f++) {
            float val;
            if (f < 8)        val = edge_feats[(size_t)(ebase + e) * 8 + f];
            else if (f < 72)  val = g_down[snd * 64 + (f - 8)];
            else if (f < 136) val = g_down[rcv * 64 + (f - 72)];
            else              val = 0.f;
            __half hi, lo; split_f16(val, hi, lo);
            int kb = f >> 4, kr = f & 15;
            int lane = (r & 7) * 4 + ((kr & 7) >> 1);
            int reg  = (r >> 3) + 2 * (kr >> 3);
            int hsel = kr & 1;
            int ai = ((mb * 16 + kb) * 32 + lane) * 4 + reg;
            *(__half*)(smem + A_HI_OFF + ai * 4 + hsel * 2) = hi;
            *(__half*)(smem + A_LO_OFF + ai * 4 + hsel * 2) = lo;
        }
    }
    __syncthreads();

    float acc[16][4];
    layer_mma2(smem, 0, 9, acc);    // Wm0
    __syncthreads();
    epi_silu_frag(smem, acc, INV_SQRT_AUG);
    layer_mma2(smem, 9, 16, acc);   // Wm1
    __syncthreads();
    epi_silu_frag(smem, acc, SIXTEENTH);
    layer_mma2(smem, 25, 16, acc);  // Wm2
    __syncthreads();
    epi_silu_frag(smem, acc, SIXTEENTH);

    // ---- final layer: two N=256 passes with register-resident TP ----
    // Permuted Wm3 fragments: thread holds wA at col j (slots ntl=0,1) and
    // wB at col 128+j (slots ntl=2,3) for the SAME j and edges — no dbuf.
    const int lane = t & 31, w = t >> 5;
    const int rq = lane >> 2, q = lane & 3;
#pragma unroll 1
    for (int p = 0; p < 2; p++) {
        layer_mma2(smem, 41 + p * 16, 16, acc);   // Wm3 half p (no sync needed: A read-only)
#pragma unroll
        for (int mb = 0; mb < 4; mb++) {
#pragma unroll
            for (int sel = 0; sel < 2; sel++) {
                int e   = mb * 16 + rq + sel * 8;
                int snd = sidx[e];
                int rcv = ridx[e];
                float y0  = eattr[e * 4 + 0];
                float yv0 = eattr[e * 4 + 1];
                float yv1 = eattr[e * 4 + 2];
                float yv2 = eattr[e * 4 + 3];
                float* m0r = g_m0 + (size_t)rcv * 256;
                float* m1r = g_m1 + (size_t)rcv * 768;
#pragma unroll
                for (int ntlA = 0; ntlA < 2; ntlA++) {
                    int j0 = w * 16 + ntlA * 8 + q * 2;
                    float wA0 = acc[mb * 4 + ntlA][sel * 2 + 0] * SIXTEENTH;
                    float wA1 = acc[mb * 4 + ntlA][sel * 2 + 1] * SIXTEENTH;
                    float wB0 = acc[mb * 4 + ntlA + 2][sel * 2 + 0] * SIXTEENTH;
                    float wB1 = acc[mb * 4 + ntlA + 2][sel * 2 + 1] * SIXTEENTH;
                    if (p == 0) {
                        // wA = w1, wB = w2
                        float2 xs = *(const float2*)(g_up_s + snd * 128 + j0);
                        atomicAdd(m0r + j0,     wA0 * xs.x * y0);
                        atomicAdd(m0r + j0 + 1, wA1 * xs.y * y0);
                        float a0 = wB0 * xs.x, a1 = wB1 * xs.y;
                        atomicAdd(m1r +   0 + j0,     a0 * yv0);
                        atomicAdd(m1r +   0 + j0 + 1, a1 * yv0);
                        atomicAdd(m1r + 256 + j0,     a0 * yv1);
                        atomicAdd(m1r + 256 + j0 + 1, a1 * yv1);
                        atomicAdd(m1r + 512 + j0,     a0 * yv2);
                        atomicAdd(m1r + 512 + j0 + 1, a1 * yv2);
                    } else {
                        // wA = w3, wB = w4
                        float2 xv0 = *(const float2*)(g_up_v + snd * 384 + j0);
                        float2 xv1 = *(const float2*)(g_up_v + snd * 384 + 128 + j0);
                        float2 xv2 = *(const float2*)(g_up_v + snd * 384 + 256 + j0);
                        float dot0 = xv0.x * yv0 + xv1.x * yv1 + xv2.x * yv2;
                        float dot1 = xv0.y * yv0 + xv1.y * yv1 + xv2.y * yv2;
                        atomicAdd(m0r + 128 + j0,     wB0 * dot0 * INV_SQRT3);
                        atomicAdd(m0r + 128 + j0 + 1, wB1 * dot1 * INV_SQRT3);
                        float a0 = wA0 * y0, a1 = wA1 * y0;
                        atomicAdd(m1r + 128 + j0,     a0 * xv0.x);
                        atomicAdd(m1r + 128 + j0 + 1, a1 * xv0.y);
                        atomicAdd(m1r + 384 + j0,     a0 * xv1.x);
                        atomicAdd(m1r + 384 + j0 + 1, a1 * xv1.y);
                        atomicAdd(m1r + 640 + j0,     a0 * xv2.x);
                        atomicAdd(m1r + 640 + j0 + 1, a1 * xv2.y);
                    }
                }
            }
        }
    }
}

// ---------------- node post-pass (unchanged) --------------------------------
__global__ __launch_bounds__(256, 2) void node_post_kernel(
    const float* __restrict__ W_lin0,
    const float* __restrict__ W_lin1,
    float* __restrict__ out)
{
    __shared__ float tile[32 * 256];
    const int nbase = blockIdx.x * 32;
    const int t = threadIdx.x;
    const int j = t & 127;
    const int g = t >> 7;

    for (int idx = t; idx < 32 * 256; idx += 256) {
        int nl = idx >> 8;
        int k  = idx & 255;
        int n  = nbase + nl;
        tile[idx] = (n < N_NODES) ? g_m0[(size_t)n * 256 + k] : 0.f;
    }
    __syncthreads();
    {
        float acc[16];
#pragma unroll
        for (int m = 0; m < 16; m++) acc[m] = 0.f;
        for (int k = 0; k < 256; k += 4) {
            float w0 = W_lin0[(k + 0) * 128 + j];
            float w1 = W_lin0[(k + 1) * 128 + j];
            float w2 = W_lin0[(k + 2) * 128 + j];
            float w3 = W_lin0[(k + 3) * 128 + j];
#pragma unroll
            for (int m = 0; m < 16; m++) {
                float4 x = *(const float4*)(tile + (g + 2 * m) * 256 + k);
                acc[m] = fmaf(x.x, w0, acc[m]);
                acc[m] = fmaf(x.y, w1, acc[m]);
                acc[m] = fmaf(x.z, w2, acc[m]);
                acc[m] = fmaf(x.w, w3, acc[m]);
            }
        }
#pragma unroll
        for (int m = 0; m < 16; m++) {
            int n = nbase + g + 2 * m;
            if (n < N_NODES) out[(size_t)n * 512 + j * 4 + 0] = acc[m] * FINAL_SCALE;
        }
    }
    for (int c = 0; c < 3; c++) {
        __syncthreads();
        for (int idx = t; idx < 32 * 256; idx += 256) {
            int nl = idx >> 8;
            int k  = idx & 255;
            int n  = nbase + nl;
            tile[idx] = (n < N_NODES) ? g_m1[(size_t)n * 768 + c * 256 + k] : 0.f;
        }
        __syncthreads();
        float acc[16];
#pragma unroll
        for (int m = 0; m < 16; m++) acc[m] = 0.f;
        for (int k = 0; k < 256; k += 4) {
            float w0 = W_lin1[(k + 0) * 128 + j];
            float w1 = W_lin1[(k + 1) * 128 + j];
            float w2 = W_lin1[(k + 2) * 128 + j];
            float w3 = W_lin1[(k + 3) * 128 + j];
#pragma unroll
            for (int m = 0; m < 16; m++) {
                float4 x = *(const float4*)(tile + (g + 2 * m) * 256 + k);
                acc[m] = fmaf(x.x, w0, acc[m]);
                acc[m] = fmaf(x.y, w1, acc[m]);
                acc[m] = fmaf(x.z, w2, acc[m]);
                acc[m] = fmaf(x.w, w3, acc[m]);
            }
        }
#pragma unroll
        for (int m = 0; m < 16; m++) {
            int n = nbase + g + 2 * m;
            if (n < N_NODES) out[(size_t)n * 512 + j * 4 + 1 + c] = acc[m] * FINAL_SCALE;
        }
    }
}

// ---------------- launch -----------------------------------------------------
extern "C" void kernel_launch(void* const* d_in, const int* in_sizes, int n_in,
                              void* d_out, int out_size)
{
    (void)in_sizes; (void)n_in; (void)out_size;
    const float* node_feats = (const float*)d_in[1];
    const float* edge_attrs = (const float*)d_in[2];
    const float* edge_feats = (const float*)d_in[3];
    const int*   edge_index = (const int*)d_in[4];
    const float* W_up0   = (const float*)d_in[5];
    const float* W_up1   = (const float*)d_in[6];
    const float* W_down  = (const float*)d_in[7];
    const float* Wm0     = (const float*)d_in[8];
    const float* Wm1     = (const float*)d_in[9];
    const float* Wm2     = (const float*)d_in[10];
    const float* Wm3     = (const float*)d_in[11];
    const float* W_lin0  = (const float*)d_in[12];
    const float* W_lin1  = (const float*)d_in[13];
    const float* W_skip0 = (const float*)d_in[14];
    const float* W_skip1 = (const float*)d_in[15];

    float* out    = (float*)d_out;
    float* out_sc = out + (size_t)N_NODES * 512;

    cudaFuncSetAttribute(node_pre_kernel,
                         cudaFuncAttributeMaxDynamicSharedMemorySize, 64 * 1024);
    cudaFuncSetAttribute(edge_kernel_mma,
                         cudaFuncAttributeMaxDynamicSharedMemorySize, EDGE_SMEM_TOTAL);

    zero_kernel<<<512, 256>>>();
    wprep_kernel<<<(73 * 1024 + 255) / 256, 256>>>(Wm0, Wm1, Wm2, Wm3);
    node_pre_kernel<<<(N_NODES + 31) / 32, 256, 64 * 1024>>>(
        node_feats, W_up0, W_up1, W_down, W_skip0, W_skip1, out_sc);
    edge_kernel_mma<<<N_EDGES / 64, 256, EDGE_SMEM_TOTAL>>>(
        edge_attrs, edge_feats, edge_index);
    node_post_kernel<<<(N_NODES + 31) / 32, 256>>>(W_lin0, W_lin1, out);
}

// round 17
// speedup vs baseline: 2.9028x; 1.0855x over previous
#include <cuda_runtime.h>
#include <cuda_fp16.h>
#include <cstdint>

#define N_NODES 10000
#define N_EDGES 160000

static __device__ float g_up_s[N_NODES * 128];
static __device__ float g_up_v[N_NODES * 384];
static __device__ float g_down[N_NODES * 64];
static __device__ float g_m0[N_NODES * 256];
static __device__ float g_m1[N_NODES * 768];

// fragment-major fp16 2-split weights:
//   [0,9)=Wm0  [9,25)=Wm1  [25,41)=Wm2  [41,57)=Wm3a  [57,73)=Wm3b (permuted)
//   [73,89)=[W_lin0 | W_lin1] combined (256 cols)
static __device__ uint2 g_wf_hi[89 * 1024];
static __device__ uint2 g_wf_lo[89 * 1024];

#define INV_SQRT_C   0.08838834764831845f
#define INV_SQRT_AUG 0.08574929257125442f
#define SIXTEENTH    0.0625f
#define INV_SQRT3    0.5773502691896258f
#define FINAL_SCALE  0.00390625f

__device__ __forceinline__ float act_silu(float a, float scale) {
    float y = a * scale;
    return y / (1.0f + __expf(-y));
}

// ---------------- HMMA m16n8k16 fp16 -> fp32 --------------------------------
__device__ __forceinline__ void mma16816(float* c, const uint32_t* a, const uint32_t* b) {
    asm volatile(
        "mma.sync.aligned.m16n8k16.row.col.f32.f16.f16.f32 "
        "{%0,%1,%2,%3},{%4,%5,%6,%7},{%8,%9},{%0,%1,%2,%3};"
        : "+f"(c[0]), "+f"(c[1]), "+f"(c[2]), "+f"(c[3])
        : "r"(a[0]), "r"(a[1]), "r"(a[2]), "r"(a[3]), "r"(b[0]), "r"(b[1]));
}

__device__ __forceinline__ uint32_t pack_half2(__half a, __half b) {
    __half2 h = __halves2half2(a, b);
    return *reinterpret_cast<uint32_t*>(&h);
}

__device__ __forceinline__ void split_f16(float v, __half& hi, __half& lo) {
    hi = __float2half_rn(v);
    lo = __float2half_rn(v - __half2float(hi));
}

// ---------------- zero scratch ----------------------------------------------
__global__ void zero_kernel() {
    float4 z = make_float4(0.f, 0.f, 0.f, 0.f);
    float4* p0 = (float4*)g_m0;
    float4* p1 = (float4*)g_m1;
    const int n0 = N_NODES * 256 / 4;
    const int n1 = N_NODES * 768 / 4;
    int idx = blockIdx.x * blockDim.x + threadIdx.x;
    int stride = gridDim.x * blockDim.x;
    for (int k = idx; k < n0; k += stride) p0[k] = z;
    for (int k = idx; k < n1; k += stride) p1[k] = z;
}

// ---------------- weight prep: fp32 -> fragment-major fp16 hi/lo ------------
__global__ void wprep_kernel(const float* __restrict__ Wm0,
                             const float* __restrict__ Wm1,
                             const float* __restrict__ Wm2,
                             const float* __restrict__ Wm3,
                             const float* __restrict__ Wl0,
                             const float* __restrict__ Wl1)
{
    int id = blockIdx.x * blockDim.x + threadIdx.x;
    if (id >= 89 * 1024) return;
    int c = id >> 10, pos = id & 1023;
    int nt = pos >> 5, lane = pos & 31;
    const float* W = nullptr; int Krows, ldw = 256, colbase = 0, kb;
    bool perm = false, lin = false;
    if (c < 9)       { W = Wm0; Krows = 136; kb = c; }
    else if (c < 25) { W = Wm1; Krows = 256; kb = c - 9; }
    else if (c < 41) { W = Wm2; Krows = 256; kb = c - 25; }
    else if (c < 57) { W = Wm3; Krows = 256; ldw = 512; kb = c - 41; perm = true; }
    else if (c < 73) { W = Wm3; Krows = 256; ldw = 512; colbase = 256; kb = c - 57; perm = true; }
    else             { Krows = 256; kb = c - 73; lin = true; }
    int ntc = nt;
    if (perm) {
        int w = nt >> 2, s = nt & 3;
        ntc = (s & 2) ? (16 + w * 2 + (s & 1)) : (w * 2 + (s & 1));
    }
    int n  = colbase + ntc * 8 + (lane >> 2);
    int k0 = kb * 16 + (lane & 3) * 2;
    float wv[4];
#pragma unroll
    for (int r = 0; r < 2; r++)
#pragma unroll
        for (int h = 0; h < 2; h++) {
            int k = k0 + r * 8 + h;
            float v;
            if (k >= Krows) v = 0.f;
            else if (lin)   v = (n < 128) ? Wl0[(size_t)k * 128 + n]
                                          : Wl1[(size_t)k * 128 + (n - 128)];
            else            v = W[(size_t)k * ldw + n];
            wv[r * 2 + h] = v;
        }
    __half h0, l0, h1, l1, h2, l2, h3, l3;
    split_f16(wv[0], h0, l0); split_f16(wv[1], h1, l1);
    split_f16(wv[2], h2, l2); split_f16(wv[3], h3, l3);
    uint2 hi, lo;
    hi.x = pack_half2(h0, h1); hi.y = pack_half2(h2, h3);
    lo.x = pack_half2(l0, l1); lo.y = pack_half2(l2, l3);
    g_wf_hi[id] = hi;
    g_wf_lo[id] = lo;
}

// ---------------- node pre-pass (unchanged FFMA path) -----------------------
__device__ __forceinline__ void dual_gemv_128(const float* __restrict__ Xs,
                                              const float* __restrict__ WA,
                                              const float* __restrict__ WB,
                                              int j, int g,
                                              float* accA, float* accB)
{
#pragma unroll
    for (int m = 0; m < 16; m++) { accA[m] = 0.f; accB[m] = 0.f; }
    for (int k = 0; k < 128; k += 4) {
        float a0 = WA[(k + 0) * 128 + j];
        float a1 = WA[(k + 1) * 128 + j];
        float a2 = WA[(k + 2) * 128 + j];
        float a3 = WA[(k + 3) * 128 + j];
        float b0 = WB[(k + 0) * 128 + j];
        float b1 = WB[(k + 1) * 128 + j];
        float b2 = WB[(k + 2) * 128 + j];
        float b3 = WB[(k + 3) * 128 + j];
#pragma unroll
        for (int m = 0; m < 16; m++) {
            float4 x = *(const float4*)(Xs + (g + 2 * m) * 128 + k);
            accA[m] = fmaf(x.x, a0, accA[m]);
            accA[m] = fmaf(x.y, a1, accA[m]);
            accA[m] = fmaf(x.z, a2, accA[m]);
            accA[m] = fmaf(x.w, a3, accA[m]);
            accB[m] = fmaf(x.x, b0, accB[m]);
            accB[m] = fmaf(x.y, b1, accB[m]);
            accB[m] = fmaf(x.z, b2, accB[m]);
            accB[m] = fmaf(x.w, b3, accB[m]);
        }
    }
}

__global__ __launch_bounds__(256, 1) void node_pre_kernel(
    const float* __restrict__ node_feats,
    const float* __restrict__ W_up0, const float* __restrict__ W_up1,
    const float* __restrict__ W_down,
    const float* __restrict__ W_skip0, const float* __restrict__ W_skip1,
    float* __restrict__ out_sc)
{
    extern __shared__ float sm[];
    float* s = sm;
    float* v = sm + 32 * 128;
    const int nbase = blockIdx.x * 32;
    const int t = threadIdx.x;

    for (int idx = t; idx < 32 * 512; idx += 256) {
        int nl = idx >> 9;
        int f  = idx & 511;
        int n  = nbase + nl;
        float val = (n < N_NODES) ? node_feats[(size_t)n * 512 + f] : 0.f;
        if (f < 128) {
            s[nl * 128 + f] = val;
        } else {
            int r = f - 128;
            int i = r / 3;
            int c = r - 3 * i;
            v[c * (32 * 128) + nl * 128 + i] = val;
        }
    }
    __syncthreads();

    const int j = t & 127;
    const int g = t >> 7;
    {
        float accA[16], accB[16];
        dual_gemv_128(s, W_skip0, W_up0, j, g, accA, accB);
#pragma unroll
        for (int m = 0; m < 16; m++) {
            int n = nbase + g + 2 * m;
            if (n < N_NODES) {
                out_sc[(size_t)n * 512 + j] = accA[m] * INV_SQRT_C;
                g_up_s[n * 128 + j]         = accB[m] * INV_SQRT_C;
            }
        }
    }
    {
        int jd = t & 63;
        int gd = t >> 6;
        float acc[8];
#pragma unroll
        for (int m = 0; m < 8; m++) acc[m] = 0.f;
        for (int k = 0; k < 128; k += 4) {
            float w0 = W_down[(k + 0) * 64 + jd];
            float w1 = W_down[(k + 1) * 64 + jd];
            float w2 = W_down[(k + 2) * 64 + jd];
            float w3 = W_down[(k + 3) * 64 + jd];
#pragma unroll
            for (int m = 0; m < 8; m++) {
                float4 x = *(const float4*)(s + (gd + 4 * m) * 128 + k);
                acc[m] = fmaf(x.x, w0, acc[m]);
                acc[m] = fmaf(x.y, w1, acc[m]);
                acc[m] = fmaf(x.z, w2, acc[m]);
                acc[m] = fmaf(x.w, w3, acc[m]);
            }
        }
#pragma unroll
        for (int m = 0; m < 8; m++) {
            int n = nbase + gd + 4 * m;
            if (n < N_NODES) g_down[n * 64 + jd] = acc[m] * INV_SQRT_C;
        }
    }
    for (int c = 0; c < 3; c++) {
        const float* vp = v + c * (32 * 128);
        float accA[16], accB[16];
        dual_gemv_128(vp, W_skip1, W_up1, j, g, accA, accB);
#pragma unroll
        for (int m = 0; m < 16; m++) {
            int n = nbase + g + 2 * m;
            if (n < N_NODES) {
                out_sc[(size_t)n * 512 + 128 + j * 3 + c] = accA[m] * INV_SQRT_C;
                g_up_v[n * 384 + c * 128 + j]             = accB[m] * INV_SQRT_C;
            }
        }
    }
}

// ---------------- shared HMMA GEMM core --------------------------------------
#define SM_SIDX    0
#define SM_RIDX    256
#define SM_EATTR   512
#define A_HI_OFF   2048
#define A_LO_OFF   34816
#define EDGE_SMEM_TOTAL 67584

// one GEMM layer into acc[16][4]; B streamed from L2 with 1-deep prefetch;
// A regs reused between hi and lo passes to stay under 128 regs.
__device__ void layer_mma2(char* smem, int cstart, int Kblocks, float acc[16][4])
{
    const int t = threadIdx.x, lane = t & 31, w = t >> 5;
#pragma unroll
    for (int i = 0; i < 16; i++) {
        acc[i][0] = 0.f; acc[i][1] = 0.f; acc[i][2] = 0.f; acc[i][3] = 0.f;
    }
    const int bbase = (cstart * 32 + w * 4) * 32 + lane;
    uint2 bh[4], bl[4];
#pragma unroll
    for (int ntl = 0; ntl < 4; ntl++) {
        bh[ntl] = g_wf_hi[bbase + ntl * 32];
        bl[ntl] = g_wf_lo[bbase + ntl * 32];
    }
#pragma unroll 1
    for (int kbl = 0; kbl < Kblocks; kbl++) {
        uint32_t av[4][4];
        uint2 nbh[4], nbl[4];
        if (kbl + 1 < Kblocks) {
            int nb = bbase + (kbl + 1) * 1024;
#pragma unroll
            for (int ntl = 0; ntl < 4; ntl++) {
                nbh[ntl] = g_wf_hi[nb + ntl * 32];
                nbl[ntl] = g_wf_lo[nb + ntl * 32];
            }
        }
        // A_HI pass: hi*w_hi and hi*w_lo
#pragma unroll
        for (int mb = 0; mb < 4; mb++) {
            int ai = ((mb * 16 + kbl) * 32 + lane) * 4;
            *(uint4*)av[mb] = *(const uint4*)(smem + A_HI_OFF + ai * 4);
        }
#pragma unroll
        for (int ntl = 0; ntl < 4; ntl++) {
            uint32_t bhh[2] = { bh[ntl].x, bh[ntl].y };
#pragma unroll
            for (int mb = 0; mb < 4; mb++) mma16816(acc[mb * 4 + ntl], av[mb], bhh);
        }
#pragma unroll
        for (int ntl = 0; ntl < 4; ntl++) {
            uint32_t bll[2] = { bl[ntl].x, bl[ntl].y };
#pragma unroll
            for (int mb = 0; mb < 4; mb++) mma16816(acc[mb * 4 + ntl], av[mb], bll);
        }
        // A_LO pass: lo*w_hi  (reuse av regs)
#pragma unroll
        for (int mb = 0; mb < 4; mb++) {
            int ai = ((mb * 16 + kbl) * 32 + lane) * 4;
            *(uint4*)av[mb] = *(const uint4*)(smem + A_LO_OFF + ai * 4);
        }
#pragma unroll
        for (int ntl = 0; ntl < 4; ntl++) {
            uint32_t bhh[2] = { bh[ntl].x, bh[ntl].y };
#pragma unroll
            for (int mb = 0; mb < 4; mb++) mma16816(acc[mb * 4 + ntl], av[mb], bhh);
        }
#pragma unroll
        for (int ntl = 0; ntl < 4; ntl++) { bh[ntl] = nbh[ntl]; bl[ntl] = nbl[ntl]; }
    }
}

// epilogue: silu(acc*scale) -> next-layer A fragments (hi/lo)
__device__ void epi_silu_frag(char* smem, float acc[16][4], float scale)
{
    const int t = threadIdx.x, lane = t & 31, w = t >> 5;
    uint32_t* ahi = (uint32_t*)(smem + A_HI_OFF);
    uint32_t* alo = (uint32_t*)(smem + A_LO_OFF);
#pragma unroll
    for (int mb = 0; mb < 4; mb++) {
#pragma unroll
        for (int ntl = 0; ntl < 4; ntl++) {
            float* c = acc[mb * 4 + ntl];
            int nt = w * 4 + ntl;
            int kb = nt >> 1;
            int regb = (nt & 1) * 2;
            float y0 = act_silu(c[0], scale), y1 = act_silu(c[1], scale);
            float y2 = act_silu(c[2], scale), y3 = act_silu(c[3], scale);
            __half h0, l0, h1, l1, h2, l2, h3, l3;
            split_f16(y0, h0, l0); split_f16(y1, h1, l1);
            split_f16(y2, h2, l2); split_f16(y3, h3, l3);
            int ai = ((mb * 16 + kb) * 32 + lane) * 4 + regb;
            ahi[ai]     = pack_half2(h0, h1);
            ahi[ai + 1] = pack_half2(h2, h3);
            alo[ai]     = pack_half2(l0, l1);
            alo[ai + 1] = pack_half2(l2, l3);
        }
    }
    __syncthreads();
}

// ---------------- HMMA edge kernel (2 CTAs/SM, register TP) -----------------
__global__ __launch_bounds__(256, 2) void edge_kernel_mma(
    const float* __restrict__ edge_attrs,
    const float* __restrict__ edge_feats,
    const int* __restrict__ edge_index)
{
    extern __shared__ char smem[];
    const int t = threadIdx.x;
    const int ebase = blockIdx.x * 64;

    int*   sidx  = (int*)(smem + SM_SIDX);
    int*   ridx  = (int*)(smem + SM_RIDX);
    float* eattr = (float*)(smem + SM_EATTR);
    if (t < 64) {
        sidx[t] = edge_index[(size_t)(ebase + t) * 2];
        ridx[t] = edge_index[(size_t)(ebase + t) * 2 + 1];
    }
    eattr[t] = edge_attrs[(size_t)ebase * 4 + t];   // 64*4 = 256 = blockDim
    __syncthreads();

    // ---- stage aug (K = 136 padded to 144) into A fragments ----
    {
        const int e = t & 63, h = t >> 6;
        const int mb = e >> 4, r = e & 15;
        const int snd = sidx[e], rcv = ridx[e];
        for (int f = h * 36; f < h * 36 + 36; f++) {
            float val;
            if (f < 8)        val = edge_feats[(size_t)(ebase + e) * 8 + f];
            else if (f < 72)  val = g_down[snd * 64 + (f - 8)];
            else if (f < 136) val = g_down[rcv * 64 + (f - 72)];
            else              val = 0.f;
            __half hi, lo; split_f16(val, hi, lo);
            int kb = f >> 4, kr = f & 15;
            int lane = (r & 7) * 4 + ((kr & 7) >> 1);
            int reg  = (r >> 3) + 2 * (kr >> 3);
            int hsel = kr & 1;
            int ai = ((mb * 16 + kb) * 32 + lane) * 4 + reg;
            *(__half*)(smem + A_HI_OFF + ai * 4 + hsel * 2) = hi;
            *(__half*)(smem + A_LO_OFF + ai * 4 + hsel * 2) = lo;
        }
    }
    __syncthreads();

    float acc[16][4];
    layer_mma2(smem, 0, 9, acc);    // Wm0
    __syncthreads();
    epi_silu_frag(smem, acc, INV_SQRT_AUG);
    layer_mma2(smem, 9, 16, acc);   // Wm1
    __syncthreads();
    epi_silu_frag(smem, acc, SIXTEENTH);
    layer_mma2(smem, 25, 16, acc);  // Wm2
    __syncthreads();
    epi_silu_frag(smem, acc, SIXTEENTH);

    // ---- final layer: two N=256 passes with register-resident TP ----
    const int lane = t & 31, w = t >> 5;
    const int rq = lane >> 2, q = lane & 3;
#pragma unroll 1
    for (int p = 0; p < 2; p++) {
        layer_mma2(smem, 41 + p * 16, 16, acc);   // Wm3 half p (A read-only)
#pragma unroll
        for (int mb = 0; mb < 4; mb++) {
#pragma unroll
            for (int sel = 0; sel < 2; sel++) {
                int e   = mb * 16 + rq + sel * 8;
                int snd = sidx[e];
                int rcv = ridx[e];
                float y0  = eattr[e * 4 + 0];
                float yv0 = eattr[e * 4 + 1];
                float yv1 = eattr[e * 4 + 2];
                float yv2 = eattr[e * 4 + 3];
                float* m0r = g_m0 + (size_t)rcv * 256;
                float* m1r = g_m1 + (size_t)rcv * 768;
#pragma unroll
                for (int ntlA = 0; ntlA < 2; ntlA++) {
                    int j0 = w * 16 + ntlA * 8 + q * 2;
                    float wA0 = acc[mb * 4 + ntlA][sel * 2 + 0] * SIXTEENTH;
                    float wA1 = acc[mb * 4 + ntlA][sel * 2 + 1] * SIXTEENTH;
                    float wB0 = acc[mb * 4 + ntlA + 2][sel * 2 + 0] * SIXTEENTH;
                    float wB1 = acc[mb * 4 + ntlA + 2][sel * 2 + 1] * SIXTEENTH;
                    if (p == 0) {
                        float2 xs = *(const float2*)(g_up_s + snd * 128 + j0);
                        atomicAdd(m0r + j0,     wA0 * xs.x * y0);
                        atomicAdd(m0r + j0 + 1, wA1 * xs.y * y0);
                        float a0 = wB0 * xs.x, a1 = wB1 * xs.y;
                        atomicAdd(m1r +   0 + j0,     a0 * yv0);
                        atomicAdd(m1r +   0 + j0 + 1, a1 * yv0);
                        atomicAdd(m1r + 256 + j0,     a0 * yv1);
                        atomicAdd(m1r + 256 + j0 + 1, a1 * yv1);
                        atomicAdd(m1r + 512 + j0,     a0 * yv2);
                        atomicAdd(m1r + 512 + j0 + 1, a1 * yv2);
                    } else {
                        float2 xv0 = *(const float2*)(g_up_v + snd * 384 + j0);
                        float2 xv1 = *(const float2*)(g_up_v + snd * 384 + 128 + j0);
                        float2 xv2 = *(const float2*)(g_up_v + snd * 384 + 256 + j0);
                        float dot0 = xv0.x * yv0 + xv1.x * yv1 + xv2.x * yv2;
                        float dot1 = xv0.y * yv0 + xv1.y * yv1 + xv2.y * yv2;
                        atomicAdd(m0r + 128 + j0,     wB0 * dot0 * INV_SQRT3);
                        atomicAdd(m0r + 128 + j0 + 1, wB1 * dot1 * INV_SQRT3);
                        float a0 = wA0 * y0, a1 = wA1 * y0;
                        atomicAdd(m1r + 128 + j0,     a0 * xv0.x);
                        atomicAdd(m1r + 128 + j0 + 1, a1 * xv0.y);
                        atomicAdd(m1r + 384 + j0,     a0 * xv1.x);
                        atomicAdd(m1r + 384 + j0 + 1, a1 * xv1.y);
                        atomicAdd(m1r + 640 + j0,     a0 * xv2.x);
                        atomicAdd(m1r + 640 + j0 + 1, a1 * xv2.y);
                    }
                }
            }
        }
    }
}

// ---------------- node post-pass: HMMA version ------------------------------
// CTA = 16 nodes -> A rows = 64 = node x {m0, m1c0, m1c1, m1c2}, K = 256.
// B = chunks 73..88 = [W_lin0 | W_lin1]; m0-rows use cols 0-127 (msg_s),
// m1c-rows use cols 128-255 (msg_v channel c). Half the D tile is discarded.
__global__ __launch_bounds__(256, 2) void node_post_mma(float* __restrict__ out)
{
    extern __shared__ char smem[];
    const int t = threadIdx.x;
    const int nbase = blockIdx.x * 16;

    // ---- stage A fragments: 64 rows x 256 k, split fp16 hi/lo ----
    {
        const int row = t & 63, h = t >> 6;
        const int node = nbase + (row >> 2), ch = row & 3;
        const float* src = (ch == 0) ? (g_m0 + (size_t)node * 256)
                                     : (g_m1 + (size_t)node * 768 + (size_t)(ch - 1) * 256);
        const int mb = row >> 4, r = row & 15;
        for (int k = h * 64; k < h * 64 + 64; k++) {
            float val = src[k];
            __half hi, lo; split_f16(val, hi, lo);
            int kb = k >> 4, kr = k & 15;
            int lane = (r & 7) * 4 + ((kr & 7) >> 1);
            int reg  = (r >> 3) + 2 * (kr >> 3);
            int hsel = kr & 1;
            int ai = ((mb * 16 + kb) * 32 + lane) * 4 + reg;
            *(__half*)(smem + A_HI_OFF + ai * 4 + hsel * 2) = hi;
            *(__half*)(smem + A_LO_OFF + ai * 4 + hsel * 2) = lo;
        }
    }
    __syncthreads();

    float acc[16][4];
    layer_mma2(smem, 73, 16, acc);

    // ---- epilogue: write useful half of D directly to out ----
    const int lane = t & 31, w = t >> 5;
    const int rq = lane >> 2, q = lane & 3;
#pragma unroll
    for (int mb = 0; mb < 4; mb++) {
#pragma unroll
        for (int ntl = 0; ntl < 4; ntl++) {
            int n0 = w * 32 + ntl * 8 + q * 2;
#pragma unroll
            for (int sel = 0; sel < 2; sel++) {
                int row  = mb * 16 + rq + sel * 8;
                int node = nbase + (row >> 2);
                int ch   = row & 3;
                float v0 = acc[mb * 4 + ntl][sel * 2 + 0] * FINAL_SCALE;
                float v1 = acc[mb * 4 + ntl][sel * 2 + 1] * FINAL_SCALE;
                if (ch == 0) {
                    if (n0 < 128) {
                        out[(size_t)node * 512 + (size_t)n0 * 4]       = v0;
                        out[(size_t)node * 512 + (size_t)(n0 + 1) * 4] = v1;
                    }
                } else {
                    if (n0 >= 128) {
                        int j = n0 - 128;
                        out[(size_t)node * 512 + (size_t)j * 4 + ch]       = v0;
                        out[(size_t)node * 512 + (size_t)(j + 1) * 4 + ch] = v1;
                    }
                }
            }
        }
    }
}

// ---------------- launch -----------------------------------------------------
extern "C" void kernel_launch(void* const* d_in, const int* in_sizes, int n_in,
                              void* d_out, int out_size)
{
    (void)in_sizes; (void)n_in; (void)out_size;
    const float* node_feats = (const float*)d_in[1];
    const float* edge_attrs = (const float*)d_in[2];
    const float* edge_feats = (const float*)d_in[3];
    const int*   edge_index = (const int*)d_in[4];
    const float* W_up0   = (const float*)d_in[5];
    const float* W_up1   = (const float*)d_in[6];
    const float* W_down  = (const float*)d_in[7];
    const float* Wm0     = (const float*)d_in[8];
    const float* Wm1     = (const float*)d_in[9];
    const float* Wm2     = (const float*)d_in[10];
    const float* Wm3     = (const float*)d_in[11];
    const float* W_lin0  = (const float*)d_in[12];
    const float* W_lin1  = (const float*)d_in[13];
    const float* W_skip0 = (const float*)d_in[14];
    const float* W_skip1 = (const float*)d_in[15];

    float* out    = (float*)d_out;
    float* out_sc = out + (size_t)N_NODES * 512;

    cudaFuncSetAttribute(node_pre_kernel,
                         cudaFuncAttributeMaxDynamicSharedMemorySize, 64 * 1024);
    cudaFuncSetAttribute(edge_kernel_mma,
                         cudaFuncAttributeMaxDynamicSharedMemorySize, EDGE_SMEM_TOTAL);
    cudaFuncSetAttribute(node_post_mma,
                         cudaFuncAttributeMaxDynamicSharedMemorySize, EDGE_SMEM_TOTAL);

    zero_kernel<<<512, 256>>>();
    wprep_kernel<<<(89 * 1024 + 255) / 256, 256>>>(Wm0, Wm1, Wm2, Wm3, W_lin0, W_lin1);
    node_pre_kernel<<<(N_NODES + 31) / 32, 256, 64 * 1024>>>(
        node_feats, W_up0, W_up1, W_down, W_skip0, W_skip1, out_sc);
    edge_kernel_mma<<<N_EDGES / 64, 256, EDGE_SMEM_TOTAL>>>(
        edge_attrs, edge_feats, edge_index);
    node_post_mma<<<N_NODES / 16, 256, EDGE_SMEM_TOTAL>>>(out);
}